// round 9
// baseline (speedup 1.0000x reference)
#include <cuda_runtime.h>
#include <cuda_bf16.h>
#include <mma.h>
#include <math.h>
#include <cstdint>

using namespace nvcuda;
typedef __nv_bfloat16 bf16;

// ---------------- problem constants ----------------
#define D_MODEL 1024
#define N_SEQ   2048
#define BATCH   2
#define HEADS   16
#define HEAD_DIM 64
#define NROWS   (BATCH * N_SEQ)          // 4096
#define SIG_SCALE 0.35355339059327373f    // 64^-0.25
#define ATT_BIAS  (-3.0f)
#define LN_EPS    1e-5f

// ---------------- device scratch (static, alloc-guard-safe) ----------------
__device__ __align__(128) bf16  g_xq [NROWS * D_MODEL];             // LN(query) bf16
__device__ __align__(128) bf16  g_kf [NROWS * D_MODEL];             // key_feats bf16
__device__ __align__(128) bf16  g_wq [D_MODEL * D_MODEL];
__device__ __align__(128) bf16  g_wkv[2 * D_MODEL * D_MODEL];       // Wk rows 0..1023, Wv rows 1024..2047
__device__ __align__(128) bf16  g_wo [D_MODEL * D_MODEL];
__device__ __align__(128) float g_proj[NROWS * 2 * D_MODEL];        // fp32 GEMM out (fits N=2048)
__device__ __align__(128) bf16  g_qn [BATCH * HEADS * N_SEQ * HEAD_DIM];
__device__ __align__(128) bf16  g_kn [BATCH * HEADS * N_SEQ * HEAD_DIM];
__device__ __align__(128) bf16  g_vt [BATCH * HEADS * N_SEQ * HEAD_DIM];
__device__ __align__(128) bf16  g_ctx[NROWS * D_MODEL];

// ---------------- cp.async helpers ----------------
__device__ __forceinline__ void cp_async16(void* smem, const void* gmem) {
    unsigned int s = (unsigned int)__cvta_generic_to_shared(smem);
    asm volatile("cp.async.cg.shared.global [%0], [%1], 16;\n" :: "r"(s), "l"(gmem));
}
__device__ __forceinline__ void cp_commit() {
    asm volatile("cp.async.commit_group;\n" ::: "memory");
}
template<int N> __device__ __forceinline__ void cp_wait() {
    asm volatile("cp.async.wait_group %0;\n" :: "n"(N) : "memory");
}

__device__ __forceinline__ float fast_sigmoid(float x) {
    // sigmoid(x) = 0.5*(1+tanh(0.5x)) ; tanh.approx err ~2^-11, buried under gamma=1e-5
    float t;
    asm("tanh.approx.f32 %0, %1;" : "=f"(t) : "f"(x * 0.5f));
    return 0.5f * (1.0f + t);
}

// ---------------- helpers ----------------
__device__ __forceinline__ float block_reduce_sum_256(float v) {
    __shared__ float sh[8];
#pragma unroll
    for (int o = 16; o > 0; o >>= 1) v += __shfl_xor_sync(0xffffffffu, v, o);
    if ((threadIdx.x & 31) == 0) sh[threadIdx.x >> 5] = v;
    __syncthreads();
    float r = 0.f;
#pragma unroll
    for (int i = 0; i < 8; i++) r += sh[i];
    __syncthreads();
    return r;
}

// ---------------- elementwise convert fp32 -> bf16 ----------------
__global__ void convert_f2bf_kernel(const float* __restrict__ in,
                                    bf16* __restrict__ out, int n4) {
    int i = blockIdx.x * blockDim.x + threadIdx.x;
    if (i >= n4) return;
    float4 v = reinterpret_cast<const float4*>(in)[i];
    __nv_bfloat162* o = reinterpret_cast<__nv_bfloat162*>(out) + i * 2;
    o[0] = __floats2bfloat162_rn(v.x, v.y);
    o[1] = __floats2bfloat162_rn(v.z, v.w);
}

// ---------------- row layernorm (D=1024) -> bf16 ----------------
__global__ void __launch_bounds__(256)
ln_rows_kernel(const float* __restrict__ x, const float* __restrict__ sc,
               const float* __restrict__ bi, bf16* __restrict__ out) {
    int row = blockIdx.x;
    const float* xr = x + (size_t)row * D_MODEL;
    int c = threadIdx.x * 4;
    float4 v = *reinterpret_cast<const float4*>(xr + c);
    float s = block_reduce_sum_256(v.x + v.y + v.z + v.w);
    float mu = s * (1.0f / D_MODEL);
    float dx = v.x - mu, dy = v.y - mu, dz = v.z - mu, dw = v.w - mu;
    float ss = block_reduce_sum_256(dx*dx + dy*dy + dz*dz + dw*dw);
    float inv = rsqrtf(ss * (1.0f / D_MODEL) + LN_EPS);
    float4 sv = *reinterpret_cast<const float4*>(sc + c);
    float4 bv = *reinterpret_cast<const float4*>(bi + c);
    __nv_bfloat162* o = reinterpret_cast<__nv_bfloat162*>(out + (size_t)row * D_MODEL + c);
    o[0] = __floats2bfloat162_rn(dx * inv * sv.x + bv.x, dy * inv * sv.y + bv.y);
    o[1] = __floats2bfloat162_rn(dz * inv * sv.z + bv.z, dw * inv * sv.w + bv.w);
}

// ---------------- final: LN(residual + gamma * att) -> fp32 ----------------
__global__ void __launch_bounds__(256)
final_ln_kernel(const float* __restrict__ resid, const float* __restrict__ att,
                const float* __restrict__ gamma, const float* __restrict__ sc,
                const float* __restrict__ bi, float* __restrict__ out) {
    int row = blockIdx.x;
    int c = threadIdx.x * 4;
    size_t off = (size_t)row * D_MODEL + c;
    float4 r = *reinterpret_cast<const float4*>(resid + off);
    float4 a = *reinterpret_cast<const float4*>(att + off);
    float4 g = *reinterpret_cast<const float4*>(gamma + c);
    float vx = r.x + g.x * a.x, vy = r.y + g.y * a.y;
    float vz = r.z + g.z * a.z, vw = r.w + g.w * a.w;
    float s = block_reduce_sum_256(vx + vy + vz + vw);
    float mu = s * (1.0f / D_MODEL);
    float dx = vx - mu, dy = vy - mu, dz = vz - mu, dw = vw - mu;
    float ss = block_reduce_sum_256(dx*dx + dy*dy + dz*dz + dw*dw);
    float inv = rsqrtf(ss * (1.0f / D_MODEL) + LN_EPS);
    float4 sv = *reinterpret_cast<const float4*>(sc + c);
    float4 bv = *reinterpret_cast<const float4*>(bi + c);
    float4 o;
    o.x = dx * inv * sv.x + bv.x;  o.y = dy * inv * sv.y + bv.y;
    o.z = dz * inv * sv.z + bv.z;  o.w = dw * inv * sv.w + bv.w;
    *reinterpret_cast<float4*>(out + off) = o;
}

// ---------------- per-head norm (Dh=64) + reshape to [B*H, N, 64] bf16 ---------
// mode 1: layernorm(qn/kn params) * SIG_SCALE ; mode 0: plain convert (V)
// proj row stride / column offset parametrized for the fused KV output.
__global__ void __launch_bounds__(256)
headnorm_kernel(const float* __restrict__ proj, int row_stride, int col_off,
                const float* __restrict__ sc, const float* __restrict__ bi,
                bf16* __restrict__ out, int mode) {
    int seg  = blockIdx.x * 8 + (threadIdx.x >> 5);   // one warp per (row, head)
    int lane = threadIdx.x & 31;
    int nrow = seg >> 4;            // / HEADS
    int h    = seg & 15;
    int b    = nrow >> 11;          // / N_SEQ
    int n    = nrow & (N_SEQ - 1);
    const float* p = proj + (size_t)nrow * row_stride + col_off + h * HEAD_DIM;
    float2 v = *reinterpret_cast<const float2*>(p + lane * 2);
    size_t oidx = ((size_t)(b * HEADS + h) * N_SEQ + n) * HEAD_DIM + lane * 2;
    if (mode == 0) {
        *reinterpret_cast<__nv_bfloat162*>(out + oidx) = __floats2bfloat162_rn(v.x, v.y);
        return;
    }
    float s = v.x + v.y;
#pragma unroll
    for (int o = 16; o > 0; o >>= 1) s += __shfl_xor_sync(0xffffffffu, s, o);
    float mu = s * (1.0f / HEAD_DIM);
    float dx = v.x - mu, dy = v.y - mu;
    float ss = dx * dx + dy * dy;
#pragma unroll
    for (int o = 16; o > 0; o >>= 1) ss += __shfl_xor_sync(0xffffffffu, ss, o);
    float inv = rsqrtf(ss * (1.0f / HEAD_DIM) + LN_EPS);
    float2 sv = *reinterpret_cast<const float2*>(sc + lane * 2);
    float2 bv = *reinterpret_cast<const float2*>(bi + lane * 2);
    float ox = (dx * inv * sv.x + bv.x) * SIG_SCALE;
    float oy = (dy * inv * sv.y + bv.y) * SIG_SCALE;
    *reinterpret_cast<__nv_bfloat162*>(out + oidx) = __floats2bfloat162_rn(ox, oy);
}

// ---------------- TN GEMM: C[M,N] = A[M,K] * B[N,K]^T  (bf16 in, fp32 out) -----
// 2-stage cp.async pipeline.
#define GBM 128
#define GBN 128
#define GBK 32
#define GPAD 40   // smem row pitch in bf16 elems (80B)

__global__ void __launch_bounds__(256)
gemm_tn_kernel(const bf16* __restrict__ A, const bf16* __restrict__ B,
               float* __restrict__ C, int M, int N, int K) {
    __shared__ __align__(128) bf16 As[2][GBM * GPAD];   // 2 x 10 KB
    __shared__ __align__(128) bf16 Bs[2][GBN * GPAD];   // 2 x 10 KB
    int bm = blockIdx.y * GBM, bn = blockIdx.x * GBN;
    int tid = threadIdx.x;
    int wid = tid >> 5;
    int wm = wid >> 1, wn = wid & 1;          // 4 x 2 warp grid -> 32 x 64 warp tile

    wmma::fragment<wmma::accumulator, 16, 16, 16, float> acc[2][4];
#pragma unroll
    for (int m = 0; m < 2; m++)
#pragma unroll
        for (int n = 0; n < 4; n++) wmma::fill_fragment(acc[m][n], 0.0f);

    const int r0 = tid >> 2, c0 = (tid & 3) * 8;   // 16B-chunk coords (row, col)

    // stage prefetch: 128 rows x 32 cols per operand = 512 chunks = 2/thread
    auto load_stage = [&](int k0, int buf) {
#pragma unroll
        for (int it = 0; it < 2; it++) {
            int r = r0 + it * 64;
            cp_async16(&As[buf][r * GPAD + c0], &A[(size_t)(bm + r) * K + k0 + c0]);
            cp_async16(&Bs[buf][r * GPAD + c0], &B[(size_t)(bn + r) * K + k0 + c0]);
        }
    };

    load_stage(0, 0);
    cp_commit();

    const int NT = K / GBK;
    int buf = 0;
    for (int t = 0; t < NT; t++) {
        if (t + 1 < NT) load_stage((t + 1) * GBK, buf ^ 1);
        cp_commit();
        cp_wait<1>();
        __syncthreads();
#pragma unroll
        for (int kk = 0; kk < GBK; kk += 16) {
            wmma::fragment<wmma::matrix_a, 16, 16, 16, bf16, wmma::row_major> af[2];
            wmma::fragment<wmma::matrix_b, 16, 16, 16, bf16, wmma::col_major> bfr[4];
#pragma unroll
            for (int m = 0; m < 2; m++)
                wmma::load_matrix_sync(af[m], &As[buf][(wm * 32 + m * 16) * GPAD + kk], GPAD);
#pragma unroll
            for (int n = 0; n < 4; n++)
                wmma::load_matrix_sync(bfr[n], &Bs[buf][(wn * 64 + n * 16) * GPAD + kk], GPAD);
#pragma unroll
            for (int m = 0; m < 2; m++)
#pragma unroll
                for (int n = 0; n < 4; n++)
                    wmma::mma_sync(acc[m][n], af[m], bfr[n], acc[m][n]);
        }
        __syncthreads();   // readers done before next prefetch overwrites this buf
        buf ^= 1;
    }
#pragma unroll
    for (int m = 0; m < 2; m++)
#pragma unroll
        for (int n = 0; n < 4; n++)
            wmma::store_matrix_sync(&C[(size_t)(bm + wm * 32 + m * 16) * N + bn + wn * 64 + n * 16],
                                    acc[m][n], N, wmma::mem_row_major);
}

// ---------------- fused sigmoid attention ----------------
// grid: (Nq/128, B*H), 256 threads (8 warps); each warp owns a 16-row Q strip.
// K/V tiles (64 rows) double-buffered with cp.async. Dynamic smem.
#define APADH 72   // bf16 pitch (144B)
#define APADF 68   // fp32 pitch (272B)
#define QTILE 128
#define KTILE 64

// smem layout offsets (bytes)
#define SA_Q   0
#define SA_K   (QTILE * APADH * 2)                         // 18432
#define SA_V   (SA_K + 2 * KTILE * APADH * 2)              // +18432
#define SA_SCR (SA_V + 2 * KTILE * APADH * 2)
#define SA_TOT (SA_SCR + 8 * 16 * APADF * 4)               // 90112 B

__global__ void __launch_bounds__(256)
attention_kernel(const bf16* __restrict__ qn, const bf16* __restrict__ kn,
                 const bf16* __restrict__ vt, bf16* __restrict__ ctx) {
    extern __shared__ __align__(128) char smem[];
    bf16*  Qs  = reinterpret_cast<bf16*>(smem + SA_Q);
    bf16*  Ks  = reinterpret_cast<bf16*>(smem + SA_K);     // 2 stages of KTILE*APADH
    bf16*  Vs  = reinterpret_cast<bf16*>(smem + SA_V);
    float* Scr = reinterpret_cast<float*>(smem + SA_SCR);

    int bh = blockIdx.y;
    int qb = blockIdx.x * QTILE;
    int b = bh >> 4, h = bh & 15;
    int tid = threadIdx.x, w = tid >> 5, lane = tid & 31;

    const bf16* qbase = qn + ((size_t)bh * N_SEQ + qb) * HEAD_DIM;
    const bf16* kbase = kn + (size_t)bh * N_SEQ * HEAD_DIM;
    const bf16* vbase = vt + (size_t)bh * N_SEQ * HEAD_DIM;

    const int r0 = tid >> 3, c0 = (tid & 7) * 8;   // 8 chunks per 64-elem row

    auto load_kv = [&](int kt, int buf) {
        bf16* kd = Ks + buf * KTILE * APADH;
        bf16* vd = Vs + buf * KTILE * APADH;
#pragma unroll
        for (int it = 0; it < 2; it++) {
            int r = r0 + it * 32;
            cp_async16(&kd[r * APADH + c0], &kbase[(size_t)(kt + r) * HEAD_DIM + c0]);
            cp_async16(&vd[r * APADH + c0], &vbase[(size_t)(kt + r) * HEAD_DIM + c0]);
        }
    };

    // prefetch K/V tile 0, then load Q synchronously (overlaps with async fill)
    load_kv(0, 0);
    cp_commit();
    for (int i = tid; i < QTILE * 8; i += 256) {     // 1024 chunks
        int r = i >> 3, c = (i & 7) * 8;
        *reinterpret_cast<uint4*>(&Qs[r * APADH + c]) =
            *reinterpret_cast<const uint4*>(&qbase[(size_t)r * HEAD_DIM + c]);
    }

    wmma::fragment<wmma::accumulator, 16, 16, 16, float> o_acc[4];
#pragma unroll
    for (int n = 0; n < 4; n++) wmma::fill_fragment(o_acc[n], 0.0f);

    float* myScr = Scr + w * 16 * APADF;
    bf16*  myP   = reinterpret_cast<bf16*>(myScr);          // 16 x APADH bf16 overlay

    const int NT = N_SEQ / KTILE;
    int buf = 0;
    for (int t = 0; t < NT; t++) {
        if (t + 1 < NT) load_kv((t + 1) * KTILE, buf ^ 1);
        cp_commit();
        cp_wait<1>();
        __syncthreads();
        const bf16* kS = Ks + buf * KTILE * APADH;
        const bf16* vS = Vs + buf * KTILE * APADH;

        // S = Q * K^T  (16 x 64 per warp)
        wmma::fragment<wmma::accumulator, 16, 16, 16, float> s_acc[4];
#pragma unroll
        for (int n = 0; n < 4; n++) wmma::fill_fragment(s_acc[n], 0.0f);
#pragma unroll
        for (int kk = 0; kk < 64; kk += 16) {
            wmma::fragment<wmma::matrix_a, 16, 16, 16, bf16, wmma::row_major> af;
            wmma::load_matrix_sync(af, &Qs[(w * 16) * APADH + kk], APADH);
#pragma unroll
            for (int n = 0; n < 4; n++) {
                wmma::fragment<wmma::matrix_b, 16, 16, 16, bf16, wmma::col_major> bfr;
                wmma::load_matrix_sync(bfr, &kS[(n * 16) * APADH + kk], APADH);
                wmma::mma_sync(s_acc[n], af, bfr, s_acc[n]);
            }
        }
        // sigmoid in registers (HW tanh.approx)
#pragma unroll
        for (int n = 0; n < 4; n++)
#pragma unroll
            for (int e = 0; e < s_acc[n].num_elements; e++)
                s_acc[n].x[e] = fast_sigmoid(s_acc[n].x[e] + ATT_BIAS);

        // re-fragment P: fp32 smem roundtrip -> bf16 matrix_a (per-warp private scratch)
#pragma unroll
        for (int n = 0; n < 4; n++)
            wmma::store_matrix_sync(myScr + n * 16, s_acc[n], APADF, wmma::mem_row_major);
        __syncwarp();
        float pv[32];
#pragma unroll
        for (int i = 0; i < 32; i++) {
            int idx = lane + i * 32;                       // 16 x 64 strip
            pv[i] = myScr[(idx >> 6) * APADF + (idx & 63)];
        }
        __syncwarp();
#pragma unroll
        for (int i = 0; i < 32; i++) {
            int idx = lane + i * 32;
            myP[(idx >> 6) * APADH + (idx & 63)] = __float2bfloat16(pv[i]);
        }
        __syncwarp();
        // O += P * V
#pragma unroll
        for (int kk = 0; kk < 64; kk += 16) {
            wmma::fragment<wmma::matrix_a, 16, 16, 16, bf16, wmma::row_major> pf;
            wmma::load_matrix_sync(pf, &myP[kk], APADH);
#pragma unroll
            for (int n = 0; n < 4; n++) {
                wmma::fragment<wmma::matrix_b, 16, 16, 16, bf16, wmma::row_major> vf;
                wmma::load_matrix_sync(vf, &vS[kk * APADH + n * 16], APADH);
                wmma::mma_sync(o_acc[n], pf, vf, o_acc[n]);
            }
        }
        __syncthreads();   // all reads of this buf done before next prefetch overwrites
        buf ^= 1;
    }

    // epilogue: O strip -> ctx bf16 in [B, Nq, H*64] layout
    __syncwarp();
#pragma unroll
    for (int n = 0; n < 4; n++)
        wmma::store_matrix_sync(myScr + n * 16, o_acc[n], APADF, wmma::mem_row_major);
    __syncwarp();
    bf16* cbase = ctx + ((size_t)(b * N_SEQ + qb + w * 16)) * D_MODEL + h * HEAD_DIM;
    for (int i = lane; i < 16 * 64; i += 32) {
        int r = i >> 6, c = i & 63;
        cbase[(size_t)r * D_MODEL + c] = __float2bfloat16(myScr[r * APADF + c]);
    }
}

// ---------------- host ----------------
static void* sym_addr(const void* sym) {
    void* p = nullptr;
    cudaGetSymbolAddress(&p, sym);
    return p;
}

extern "C" void kernel_launch(void* const* d_in, const int* in_sizes, int n_in,
                              void* d_out, int out_size) {
    const float* query_feats  = (const float*)d_in[0];
    const float* key_feats    = (const float*)d_in[1];
    const float* Wq           = (const float*)d_in[2];
    const float* Wk           = (const float*)d_in[3];
    const float* Wv           = (const float*)d_in[4];
    const float* Wo           = (const float*)d_in[5];
    const float* qn_scale     = (const float*)d_in[6];
    const float* qn_bias      = (const float*)d_in[7];
    const float* kn_scale     = (const float*)d_in[8];
    const float* kn_bias      = (const float*)d_in[9];
    const float* ln_q_scale   = (const float*)d_in[10];
    const float* ln_q_bias    = (const float*)d_in[11];
    const float* ln_out_scale = (const float*)d_in[12];
    const float* ln_out_bias  = (const float*)d_in[13];
    const float* gamma        = (const float*)d_in[14];
    float* out = (float*)d_out;

    bf16*  xq   = (bf16*) sym_addr(g_xq);
    bf16*  kf   = (bf16*) sym_addr(g_kf);
    bf16*  wq   = (bf16*) sym_addr(g_wq);
    bf16*  wkv  = (bf16*) sym_addr(g_wkv);
    bf16*  wo   = (bf16*) sym_addr(g_wo);
    float* proj = (float*)sym_addr(g_proj);
    bf16*  qn   = (bf16*) sym_addr(g_qn);
    bf16*  kn   = (bf16*) sym_addr(g_kn);
    bf16*  vt   = (bf16*) sym_addr(g_vt);
    bf16*  ctx  = (bf16*) sym_addr(g_ctx);

    const int featN4 = NROWS * D_MODEL / 4;      // 1,048,576 vec4
    const int wN4    = D_MODEL * D_MODEL / 4;    // 262,144 vec4

    // bf16 conversions (Wk|Wv stacked into one [2048,1024] matrix)
    convert_f2bf_kernel<<<featN4 / 256, 256>>>(key_feats, kf, featN4);
    convert_f2bf_kernel<<<wN4 / 256, 256>>>(Wq, wq, wN4);
    convert_f2bf_kernel<<<wN4 / 256, 256>>>(Wk, wkv, wN4);
    convert_f2bf_kernel<<<wN4 / 256, 256>>>(Wv, wkv + D_MODEL * D_MODEL, wN4);
    convert_f2bf_kernel<<<wN4 / 256, 256>>>(Wo, wo, wN4);

    // pre-LN of query
    ln_rows_kernel<<<NROWS, 256>>>(query_feats, ln_q_scale, ln_q_bias, xq);

    const int segBlocks = (NROWS * HEADS) / 8;   // 8192

    // Q projection + head-norm
    gemm_tn_kernel<<<dim3(D_MODEL / GBN, NROWS / GBM), 256>>>(xq, wq, proj, NROWS, D_MODEL, D_MODEL);
    headnorm_kernel<<<segBlocks, 256>>>(proj, D_MODEL, 0, qn_scale, qn_bias, qn, 1);

    // fused K|V projection (N=2048), then head-norm / reshape
    gemm_tn_kernel<<<dim3(2 * D_MODEL / GBN, NROWS / GBM), 256>>>(kf, wkv, proj, NROWS, 2 * D_MODEL, D_MODEL);
    headnorm_kernel<<<segBlocks, 256>>>(proj, 2 * D_MODEL, 0,       kn_scale, kn_bias, kn, 1);
    headnorm_kernel<<<segBlocks, 256>>>(proj, 2 * D_MODEL, D_MODEL, nullptr,  nullptr, vt, 0);

    // fused sigmoid attention (dynamic smem: 90112 B)
    cudaFuncSetAttribute(attention_kernel, cudaFuncAttributeMaxDynamicSharedMemorySize, SA_TOT);
    attention_kernel<<<dim3(N_SEQ / QTILE, BATCH * HEADS), 256, SA_TOT>>>(qn, kn, vt, ctx);

    // output projection
    gemm_tn_kernel<<<dim3(D_MODEL / GBN, NROWS / GBM), 256>>>(ctx, wo, proj, NROWS, D_MODEL, D_MODEL);

    // residual + gamma scale + post-LN
    final_ln_kernel<<<NROWS, 256>>>(query_feats, proj, gamma,
                                    ln_out_scale, ln_out_bias, out);
    (void)in_sizes; (void)n_in; (void)out_size;
}

// round 10
// speedup vs baseline: 1.0016x; 1.0016x over previous
#include <cuda_runtime.h>
#include <cuda_bf16.h>
#include <mma.h>
#include <math.h>
#include <cstdint>

using namespace nvcuda;
typedef __nv_bfloat16 bf16;

// ---------------- problem constants ----------------
#define D_MODEL 1024
#define N_SEQ   2048
#define BATCH   2
#define HEADS   16
#define HEAD_DIM 64
#define NROWS   (BATCH * N_SEQ)          // 4096
#define SIG_SCALE 0.35355339059327373f    // 64^-0.25
#define ATT_BIAS  (-3.0f)
#define LN_EPS    1e-5f

// ---------------- device scratch (static, alloc-guard-safe) ----------------
__device__ __align__(128) bf16  g_xq [NROWS * D_MODEL];             // LN(query) bf16
__device__ __align__(128) bf16  g_kf [NROWS * D_MODEL];             // key_feats bf16
__device__ __align__(128) bf16  g_wq [D_MODEL * D_MODEL];
__device__ __align__(128) bf16  g_wkv[2 * D_MODEL * D_MODEL];       // Wk rows 0..1023, Wv rows 1024..2047
__device__ __align__(128) bf16  g_wo [D_MODEL * D_MODEL];
__device__ __align__(128) float g_proj[NROWS * 2 * D_MODEL];        // fp32 GEMM out (fits N=2048)
__device__ __align__(128) bf16  g_qn [BATCH * HEADS * N_SEQ * HEAD_DIM];
__device__ __align__(128) bf16  g_kn [BATCH * HEADS * N_SEQ * HEAD_DIM];
__device__ __align__(128) bf16  g_vt [BATCH * HEADS * N_SEQ * HEAD_DIM];
__device__ __align__(128) bf16  g_ctx[NROWS * D_MODEL];

// ---------------- cp.async helpers ----------------
__device__ __forceinline__ void cp_async16(void* smem, const void* gmem) {
    unsigned int s = (unsigned int)__cvta_generic_to_shared(smem);
    asm volatile("cp.async.cg.shared.global [%0], [%1], 16;\n" :: "r"(s), "l"(gmem));
}
__device__ __forceinline__ void cp_commit() {
    asm volatile("cp.async.commit_group;\n" ::: "memory");
}
template<int N> __device__ __forceinline__ void cp_wait() {
    asm volatile("cp.async.wait_group %0;\n" :: "n"(N) : "memory");
}

__device__ __forceinline__ float fast_sigmoid(float x) {
    // sigmoid(x) = 0.5*(1+tanh(0.5x)) ; tanh.approx err ~2^-11, buried under gamma=1e-5
    float t;
    asm("tanh.approx.f32 %0, %1;" : "=f"(t) : "f"(x * 0.5f));
    return 0.5f * (1.0f + t);
}

// ---------------- helpers ----------------
__device__ __forceinline__ float block_reduce_sum_256(float v) {
    __shared__ float sh[8];
#pragma unroll
    for (int o = 16; o > 0; o >>= 1) v += __shfl_xor_sync(0xffffffffu, v, o);
    if ((threadIdx.x & 31) == 0) sh[threadIdx.x >> 5] = v;
    __syncthreads();
    float r = 0.f;
#pragma unroll
    for (int i = 0; i < 8; i++) r += sh[i];
    __syncthreads();
    return r;
}

// ---------------- elementwise convert fp32 -> bf16 ----------------
__global__ void convert_f2bf_kernel(const float* __restrict__ in,
                                    bf16* __restrict__ out, int n4) {
    int i = blockIdx.x * blockDim.x + threadIdx.x;
    if (i >= n4) return;
    float4 v = reinterpret_cast<const float4*>(in)[i];
    __nv_bfloat162* o = reinterpret_cast<__nv_bfloat162*>(out) + i * 2;
    o[0] = __floats2bfloat162_rn(v.x, v.y);
    o[1] = __floats2bfloat162_rn(v.z, v.w);
}

// ---------------- row layernorm (D=1024) -> bf16 ----------------
__global__ void __launch_bounds__(256)
ln_rows_kernel(const float* __restrict__ x, const float* __restrict__ sc,
               const float* __restrict__ bi, bf16* __restrict__ out) {
    int row = blockIdx.x;
    const float* xr = x + (size_t)row * D_MODEL;
    int c = threadIdx.x * 4;
    float4 v = *reinterpret_cast<const float4*>(xr + c);
    float s = block_reduce_sum_256(v.x + v.y + v.z + v.w);
    float mu = s * (1.0f / D_MODEL);
    float dx = v.x - mu, dy = v.y - mu, dz = v.z - mu, dw = v.w - mu;
    float ss = block_reduce_sum_256(dx*dx + dy*dy + dz*dz + dw*dw);
    float inv = rsqrtf(ss * (1.0f / D_MODEL) + LN_EPS);
    float4 sv = *reinterpret_cast<const float4*>(sc + c);
    float4 bv = *reinterpret_cast<const float4*>(bi + c);
    __nv_bfloat162* o = reinterpret_cast<__nv_bfloat162*>(out + (size_t)row * D_MODEL + c);
    o[0] = __floats2bfloat162_rn(dx * inv * sv.x + bv.x, dy * inv * sv.y + bv.y);
    o[1] = __floats2bfloat162_rn(dz * inv * sv.z + bv.z, dw * inv * sv.w + bv.w);
}

// ---------------- final: LN(residual + gamma * att) -> fp32 ----------------
__global__ void __launch_bounds__(256)
final_ln_kernel(const float* __restrict__ resid, const float* __restrict__ att,
                const float* __restrict__ gamma, const float* __restrict__ sc,
                const float* __restrict__ bi, float* __restrict__ out) {
    int row = blockIdx.x;
    int c = threadIdx.x * 4;
    size_t off = (size_t)row * D_MODEL + c;
    float4 r = *reinterpret_cast<const float4*>(resid + off);
    float4 a = *reinterpret_cast<const float4*>(att + off);
    float4 g = *reinterpret_cast<const float4*>(gamma + c);
    float vx = r.x + g.x * a.x, vy = r.y + g.y * a.y;
    float vz = r.z + g.z * a.z, vw = r.w + g.w * a.w;
    float s = block_reduce_sum_256(vx + vy + vz + vw);
    float mu = s * (1.0f / D_MODEL);
    float dx = vx - mu, dy = vy - mu, dz = vz - mu, dw = vw - mu;
    float ss = block_reduce_sum_256(dx*dx + dy*dy + dz*dz + dw*dw);
    float inv = rsqrtf(ss * (1.0f / D_MODEL) + LN_EPS);
    float4 sv = *reinterpret_cast<const float4*>(sc + c);
    float4 bv = *reinterpret_cast<const float4*>(bi + c);
    float4 o;
    o.x = dx * inv * sv.x + bv.x;  o.y = dy * inv * sv.y + bv.y;
    o.z = dz * inv * sv.z + bv.z;  o.w = dw * inv * sv.w + bv.w;
    *reinterpret_cast<float4*>(out + off) = o;
}

// ---------------- per-head norm (Dh=64) + reshape to [B*H, N, 64] bf16 ---------
// mode 1: layernorm(qn/kn params) * SIG_SCALE ; mode 0: plain convert (V)
// proj row stride / column offset parametrized for the fused KV output.
__global__ void __launch_bounds__(256)
headnorm_kernel(const float* __restrict__ proj, int row_stride, int col_off,
                const float* __restrict__ sc, const float* __restrict__ bi,
                bf16* __restrict__ out, int mode) {
    int seg  = blockIdx.x * 8 + (threadIdx.x >> 5);   // one warp per (row, head)
    int lane = threadIdx.x & 31;
    int nrow = seg >> 4;            // / HEADS
    int h    = seg & 15;
    int b    = nrow >> 11;          // / N_SEQ
    int n    = nrow & (N_SEQ - 1);
    const float* p = proj + (size_t)nrow * row_stride + col_off + h * HEAD_DIM;
    float2 v = *reinterpret_cast<const float2*>(p + lane * 2);
    size_t oidx = ((size_t)(b * HEADS + h) * N_SEQ + n) * HEAD_DIM + lane * 2;
    if (mode == 0) {
        *reinterpret_cast<__nv_bfloat162*>(out + oidx) = __floats2bfloat162_rn(v.x, v.y);
        return;
    }
    float s = v.x + v.y;
#pragma unroll
    for (int o = 16; o > 0; o >>= 1) s += __shfl_xor_sync(0xffffffffu, s, o);
    float mu = s * (1.0f / HEAD_DIM);
    float dx = v.x - mu, dy = v.y - mu;
    float ss = dx * dx + dy * dy;
#pragma unroll
    for (int o = 16; o > 0; o >>= 1) ss += __shfl_xor_sync(0xffffffffu, ss, o);
    float inv = rsqrtf(ss * (1.0f / HEAD_DIM) + LN_EPS);
    float2 sv = *reinterpret_cast<const float2*>(sc + lane * 2);
    float2 bv = *reinterpret_cast<const float2*>(bi + lane * 2);
    float ox = (dx * inv * sv.x + bv.x) * SIG_SCALE;
    float oy = (dy * inv * sv.y + bv.y) * SIG_SCALE;
    *reinterpret_cast<__nv_bfloat162*>(out + oidx) = __floats2bfloat162_rn(ox, oy);
}

// ---------------- TN GEMM: C[M,N] = A[M,K] * B[N,K]^T  (bf16 in, fp32 out) -----
// 2-stage cp.async pipeline.
#define GBM 128
#define GBN 128
#define GBK 32
#define GPAD 40   // smem row pitch in bf16 elems (80B)

__global__ void __launch_bounds__(256)
gemm_tn_kernel(const bf16* __restrict__ A, const bf16* __restrict__ B,
               float* __restrict__ C, int M, int N, int K) {
    __shared__ __align__(128) bf16 As[2][GBM * GPAD];   // 2 x 10 KB
    __shared__ __align__(128) bf16 Bs[2][GBN * GPAD];   // 2 x 10 KB
    int bm = blockIdx.y * GBM, bn = blockIdx.x * GBN;
    int tid = threadIdx.x;
    int wid = tid >> 5;
    int wm = wid >> 1, wn = wid & 1;          // 4 x 2 warp grid -> 32 x 64 warp tile

    wmma::fragment<wmma::accumulator, 16, 16, 16, float> acc[2][4];
#pragma unroll
    for (int m = 0; m < 2; m++)
#pragma unroll
        for (int n = 0; n < 4; n++) wmma::fill_fragment(acc[m][n], 0.0f);

    const int r0 = tid >> 2, c0 = (tid & 3) * 8;   // 16B-chunk coords (row, col)

    // stage prefetch: 128 rows x 32 cols per operand = 512 chunks = 2/thread
    auto load_stage = [&](int k0, int buf) {
#pragma unroll
        for (int it = 0; it < 2; it++) {
            int r = r0 + it * 64;
            cp_async16(&As[buf][r * GPAD + c0], &A[(size_t)(bm + r) * K + k0 + c0]);
            cp_async16(&Bs[buf][r * GPAD + c0], &B[(size_t)(bn + r) * K + k0 + c0]);
        }
    };

    load_stage(0, 0);
    cp_commit();

    const int NT = K / GBK;
    int buf = 0;
    for (int t = 0; t < NT; t++) {
        if (t + 1 < NT) load_stage((t + 1) * GBK, buf ^ 1);
        cp_commit();
        cp_wait<1>();
        __syncthreads();
#pragma unroll
        for (int kk = 0; kk < GBK; kk += 16) {
            wmma::fragment<wmma::matrix_a, 16, 16, 16, bf16, wmma::row_major> af[2];
            wmma::fragment<wmma::matrix_b, 16, 16, 16, bf16, wmma::col_major> bfr[4];
#pragma unroll
            for (int m = 0; m < 2; m++)
                wmma::load_matrix_sync(af[m], &As[buf][(wm * 32 + m * 16) * GPAD + kk], GPAD);
#pragma unroll
            for (int n = 0; n < 4; n++)
                wmma::load_matrix_sync(bfr[n], &Bs[buf][(wn * 64 + n * 16) * GPAD + kk], GPAD);
#pragma unroll
            for (int m = 0; m < 2; m++)
#pragma unroll
                for (int n = 0; n < 4; n++)
                    wmma::mma_sync(acc[m][n], af[m], bfr[n], acc[m][n]);
        }
        __syncthreads();   // readers done before next prefetch overwrites this buf
        buf ^= 1;
    }
#pragma unroll
    for (int m = 0; m < 2; m++)
#pragma unroll
        for (int n = 0; n < 4; n++)
            wmma::store_matrix_sync(&C[(size_t)(bm + wm * 32 + m * 16) * N + bn + wn * 64 + n * 16],
                                    acc[m][n], N, wmma::mem_row_major);
}

// ---------------- fused sigmoid attention ----------------
// grid: (Nq/128, B*H), 256 threads (8 warps); each warp owns a 16-row Q strip.
// K/V tiles (64 rows) double-buffered with cp.async. Dynamic smem.
#define APADH 72   // bf16 pitch (144B)
#define APADF 68   // fp32 pitch (272B)
#define QTILE 128
#define KTILE 64

// smem layout offsets (bytes)
#define SA_Q   0
#define SA_K   (QTILE * APADH * 2)                         // 18432
#define SA_V   (SA_K + 2 * KTILE * APADH * 2)              // +18432
#define SA_SCR (SA_V + 2 * KTILE * APADH * 2)
#define SA_TOT (SA_SCR + 8 * 16 * APADF * 4)               // 90112 B

__global__ void __launch_bounds__(256)
attention_kernel(const bf16* __restrict__ qn, const bf16* __restrict__ kn,
                 const bf16* __restrict__ vt, bf16* __restrict__ ctx) {
    extern __shared__ __align__(128) char smem[];
    bf16*  Qs  = reinterpret_cast<bf16*>(smem + SA_Q);
    bf16*  Ks  = reinterpret_cast<bf16*>(smem + SA_K);     // 2 stages of KTILE*APADH
    bf16*  Vs  = reinterpret_cast<bf16*>(smem + SA_V);
    float* Scr = reinterpret_cast<float*>(smem + SA_SCR);

    int bh = blockIdx.y;
    int qb = blockIdx.x * QTILE;
    int b = bh >> 4, h = bh & 15;
    int tid = threadIdx.x, w = tid >> 5, lane = tid & 31;

    const bf16* qbase = qn + ((size_t)bh * N_SEQ + qb) * HEAD_DIM;
    const bf16* kbase = kn + (size_t)bh * N_SEQ * HEAD_DIM;
    const bf16* vbase = vt + (size_t)bh * N_SEQ * HEAD_DIM;

    const int r0 = tid >> 3, c0 = (tid & 7) * 8;   // 8 chunks per 64-elem row

    auto load_kv = [&](int kt, int buf) {
        bf16* kd = Ks + buf * KTILE * APADH;
        bf16* vd = Vs + buf * KTILE * APADH;
#pragma unroll
        for (int it = 0; it < 2; it++) {
            int r = r0 + it * 32;
            cp_async16(&kd[r * APADH + c0], &kbase[(size_t)(kt + r) * HEAD_DIM + c0]);
            cp_async16(&vd[r * APADH + c0], &vbase[(size_t)(kt + r) * HEAD_DIM + c0]);
        }
    };

    // prefetch K/V tile 0, then load Q synchronously (overlaps with async fill)
    load_kv(0, 0);
    cp_commit();
    for (int i = tid; i < QTILE * 8; i += 256) {     // 1024 chunks
        int r = i >> 3, c = (i & 7) * 8;
        *reinterpret_cast<uint4*>(&Qs[r * APADH + c]) =
            *reinterpret_cast<const uint4*>(&qbase[(size_t)r * HEAD_DIM + c]);
    }

    wmma::fragment<wmma::accumulator, 16, 16, 16, float> o_acc[4];
#pragma unroll
    for (int n = 0; n < 4; n++) wmma::fill_fragment(o_acc[n], 0.0f);

    float* myScr = Scr + w * 16 * APADF;
    bf16*  myP   = reinterpret_cast<bf16*>(myScr);          // 16 x APADH bf16 overlay

    const int NT = N_SEQ / KTILE;
    int buf = 0;
    for (int t = 0; t < NT; t++) {
        if (t + 1 < NT) load_kv((t + 1) * KTILE, buf ^ 1);
        cp_commit();
        cp_wait<1>();
        __syncthreads();
        const bf16* kS = Ks + buf * KTILE * APADH;
        const bf16* vS = Vs + buf * KTILE * APADH;

        // S = Q * K^T  (16 x 64 per warp)
        wmma::fragment<wmma::accumulator, 16, 16, 16, float> s_acc[4];
#pragma unroll
        for (int n = 0; n < 4; n++) wmma::fill_fragment(s_acc[n], 0.0f);
#pragma unroll
        for (int kk = 0; kk < 64; kk += 16) {
            wmma::fragment<wmma::matrix_a, 16, 16, 16, bf16, wmma::row_major> af;
            wmma::load_matrix_sync(af, &Qs[(w * 16) * APADH + kk], APADH);
#pragma unroll
            for (int n = 0; n < 4; n++) {
                wmma::fragment<wmma::matrix_b, 16, 16, 16, bf16, wmma::col_major> bfr;
                wmma::load_matrix_sync(bfr, &kS[(n * 16) * APADH + kk], APADH);
                wmma::mma_sync(s_acc[n], af, bfr, s_acc[n]);
            }
        }
        // sigmoid in registers (HW tanh.approx)
#pragma unroll
        for (int n = 0; n < 4; n++)
#pragma unroll
            for (int e = 0; e < s_acc[n].num_elements; e++)
                s_acc[n].x[e] = fast_sigmoid(s_acc[n].x[e] + ATT_BIAS);

        // re-fragment P: fp32 smem roundtrip -> bf16 matrix_a (per-warp private scratch)
#pragma unroll
        for (int n = 0; n < 4; n++)
            wmma::store_matrix_sync(myScr + n * 16, s_acc[n], APADF, wmma::mem_row_major);
        __syncwarp();
        float pv[32];
#pragma unroll
        for (int i = 0; i < 32; i++) {
            int idx = lane + i * 32;                       // 16 x 64 strip
            pv[i] = myScr[(idx >> 6) * APADF + (idx & 63)];
        }
        __syncwarp();
#pragma unroll
        for (int i = 0; i < 32; i++) {
            int idx = lane + i * 32;
            myP[(idx >> 6) * APADH + (idx & 63)] = __float2bfloat16(pv[i]);
        }
        __syncwarp();
        // O += P * V
#pragma unroll
        for (int kk = 0; kk < 64; kk += 16) {
            wmma::fragment<wmma::matrix_a, 16, 16, 16, bf16, wmma::row_major> pf;
            wmma::load_matrix_sync(pf, &myP[kk], APADH);
#pragma unroll
            for (int n = 0; n < 4; n++) {
                wmma::fragment<wmma::matrix_b, 16, 16, 16, bf16, wmma::row_major> vf;
                wmma::load_matrix_sync(vf, &vS[kk * APADH + n * 16], APADH);
                wmma::mma_sync(o_acc[n], pf, vf, o_acc[n]);
            }
        }
        __syncthreads();   // all reads of this buf done before next prefetch overwrites
        buf ^= 1;
    }

    // epilogue: O strip -> ctx bf16 in [B, Nq, H*64] layout
    __syncwarp();
#pragma unroll
    for (int n = 0; n < 4; n++)
        wmma::store_matrix_sync(myScr + n * 16, o_acc[n], APADF, wmma::mem_row_major);
    __syncwarp();
    bf16* cbase = ctx + ((size_t)(b * N_SEQ + qb + w * 16)) * D_MODEL + h * HEAD_DIM;
    for (int i = lane; i < 16 * 64; i += 32) {
        int r = i >> 6, c = i & 63;
        cbase[(size_t)r * D_MODEL + c] = __float2bfloat16(myScr[r * APADF + c]);
    }
}

// ---------------- host ----------------
static void* sym_addr(const void* sym) {
    void* p = nullptr;
    cudaGetSymbolAddress(&p, sym);
    return p;
}

extern "C" void kernel_launch(void* const* d_in, const int* in_sizes, int n_in,
                              void* d_out, int out_size) {
    const float* query_feats  = (const float*)d_in[0];
    const float* key_feats    = (const float*)d_in[1];
    const float* Wq           = (const float*)d_in[2];
    const float* Wk           = (const float*)d_in[3];
    const float* Wv           = (const float*)d_in[4];
    const float* Wo           = (const float*)d_in[5];
    const float* qn_scale     = (const float*)d_in[6];
    const float* qn_bias      = (const float*)d_in[7];
    const float* kn_scale     = (const float*)d_in[8];
    const float* kn_bias      = (const float*)d_in[9];
    const float* ln_q_scale   = (const float*)d_in[10];
    const float* ln_q_bias    = (const float*)d_in[11];
    const float* ln_out_scale = (const float*)d_in[12];
    const float* ln_out_bias  = (const float*)d_in[13];
    const float* gamma        = (const float*)d_in[14];
    float* out = (float*)d_out;

    bf16*  xq   = (bf16*) sym_addr(g_xq);
    bf16*  kf   = (bf16*) sym_addr(g_kf);
    bf16*  wq   = (bf16*) sym_addr(g_wq);
    bf16*  wkv  = (bf16*) sym_addr(g_wkv);
    bf16*  wo   = (bf16*) sym_addr(g_wo);
    float* proj = (float*)sym_addr(g_proj);
    bf16*  qn   = (bf16*) sym_addr(g_qn);
    bf16*  kn   = (bf16*) sym_addr(g_kn);
    bf16*  vt   = (bf16*) sym_addr(g_vt);
    bf16*  ctx  = (bf16*) sym_addr(g_ctx);

    const int featN4 = NROWS * D_MODEL / 4;      // 1,048,576 vec4
    const int wN4    = D_MODEL * D_MODEL / 4;    // 262,144 vec4

    // bf16 conversions (Wk|Wv stacked into one [2048,1024] matrix)
    convert_f2bf_kernel<<<featN4 / 256, 256>>>(key_feats, kf, featN4);
    convert_f2bf_kernel<<<wN4 / 256, 256>>>(Wq, wq, wN4);
    convert_f2bf_kernel<<<wN4 / 256, 256>>>(Wk, wkv, wN4);
    convert_f2bf_kernel<<<wN4 / 256, 256>>>(Wv, wkv + D_MODEL * D_MODEL, wN4);
    convert_f2bf_kernel<<<wN4 / 256, 256>>>(Wo, wo, wN4);

    // pre-LN of query
    ln_rows_kernel<<<NROWS, 256>>>(query_feats, ln_q_scale, ln_q_bias, xq);

    const int segBlocks = (NROWS * HEADS) / 8;   // 8192

    // Q projection + head-norm
    gemm_tn_kernel<<<dim3(D_MODEL / GBN, NROWS / GBM), 256>>>(xq, wq, proj, NROWS, D_MODEL, D_MODEL);
    headnorm_kernel<<<segBlocks, 256>>>(proj, D_MODEL, 0, qn_scale, qn_bias, qn, 1);

    // fused K|V projection (N=2048), then head-norm / reshape
    gemm_tn_kernel<<<dim3(2 * D_MODEL / GBN, NROWS / GBM), 256>>>(kf, wkv, proj, NROWS, 2 * D_MODEL, D_MODEL);
    headnorm_kernel<<<segBlocks, 256>>>(proj, 2 * D_MODEL, 0,       kn_scale, kn_bias, kn, 1);
    headnorm_kernel<<<segBlocks, 256>>>(proj, 2 * D_MODEL, D_MODEL, nullptr,  nullptr, vt, 0);

    // fused sigmoid attention (dynamic smem: 90112 B)
    cudaFuncSetAttribute(attention_kernel, cudaFuncAttributeMaxDynamicSharedMemorySize, SA_TOT);
    attention_kernel<<<dim3(N_SEQ / QTILE, BATCH * HEADS), 256, SA_TOT>>>(qn, kn, vt, ctx);

    // output projection
    gemm_tn_kernel<<<dim3(D_MODEL / GBN, NROWS / GBM), 256>>>(ctx, wo, proj, NROWS, D_MODEL, D_MODEL);

    // residual + gamma scale + post-LN
    final_ln_kernel<<<NROWS, 256>>>(query_feats, proj, gamma,
                                    ln_out_scale, ln_out_bias, out);
    (void)in_sizes; (void)n_in; (void)out_size;
}

// round 11
// speedup vs baseline: 1.0029x; 1.0013x over previous
#include <cuda_runtime.h>
#include <cuda_bf16.h>
#include <mma.h>
#include <math.h>
#include <cstdint>

using namespace nvcuda;
typedef __nv_bfloat16 bf16;

// ---------------- problem constants ----------------
#define D_MODEL 1024
#define N_SEQ   2048
#define BATCH   2
#define HEADS   16
#define HEAD_DIM 64
#define NROWS   (BATCH * N_SEQ)          // 4096
#define SIG_SCALE 0.35355339059327373f    // 64^-0.25
#define ATT_BIAS  (-3.0f)
#define LN_EPS    1e-5f

// ---------------- device scratch (static, alloc-guard-safe) ----------------
__device__ __align__(128) bf16  g_xq [NROWS * D_MODEL];             // LN(query) bf16
__device__ __align__(128) bf16  g_kf [NROWS * D_MODEL];             // key_feats bf16
__device__ __align__(128) bf16  g_wq [D_MODEL * D_MODEL];
__device__ __align__(128) bf16  g_wkv[2 * D_MODEL * D_MODEL];       // Wk rows 0..1023, Wv rows 1024..2047
__device__ __align__(128) bf16  g_wo [D_MODEL * D_MODEL];
__device__ __align__(128) float g_proj[NROWS * 2 * D_MODEL];        // fp32 GEMM out (fits N=2048)
__device__ __align__(128) bf16  g_qn [BATCH * HEADS * N_SEQ * HEAD_DIM];
__device__ __align__(128) bf16  g_kn [BATCH * HEADS * N_SEQ * HEAD_DIM];
__device__ __align__(128) bf16  g_vt [BATCH * HEADS * N_SEQ * HEAD_DIM];
__device__ __align__(128) bf16  g_ctx[NROWS * D_MODEL];

// ---------------- cp.async helpers ----------------
__device__ __forceinline__ void cp_async16(void* smem, const void* gmem) {
    unsigned int s = (unsigned int)__cvta_generic_to_shared(smem);
    asm volatile("cp.async.cg.shared.global [%0], [%1], 16;\n" :: "r"(s), "l"(gmem));
}
__device__ __forceinline__ void cp_commit() {
    asm volatile("cp.async.commit_group;\n" ::: "memory");
}
template<int N> __device__ __forceinline__ void cp_wait() {
    asm volatile("cp.async.wait_group %0;\n" :: "n"(N) : "memory");
}

__device__ __forceinline__ float fast_sigmoid(float x) {
    // sigmoid(x) = 0.5*(1+tanh(0.5x)) ; tanh.approx err ~2^-11, buried under gamma=1e-5
    float t;
    asm("tanh.approx.f32 %0, %1;" : "=f"(t) : "f"(x * 0.5f));
    return 0.5f * (1.0f + t);
}

// ---------------- helpers ----------------
__device__ __forceinline__ float block_reduce_sum_256(float v) {
    __shared__ float sh[8];
#pragma unroll
    for (int o = 16; o > 0; o >>= 1) v += __shfl_xor_sync(0xffffffffu, v, o);
    if ((threadIdx.x & 31) == 0) sh[threadIdx.x >> 5] = v;
    __syncthreads();
    float r = 0.f;
#pragma unroll
    for (int i = 0; i < 8; i++) r += sh[i];
    __syncthreads();
    return r;
}

// ---------------- elementwise convert fp32 -> bf16 ----------------
__global__ void convert_f2bf_kernel(const float* __restrict__ in,
                                    bf16* __restrict__ out, int n4) {
    int i = blockIdx.x * blockDim.x + threadIdx.x;
    if (i >= n4) return;
    float4 v = reinterpret_cast<const float4*>(in)[i];
    __nv_bfloat162* o = reinterpret_cast<__nv_bfloat162*>(out) + i * 2;
    o[0] = __floats2bfloat162_rn(v.x, v.y);
    o[1] = __floats2bfloat162_rn(v.z, v.w);
}

// ---------------- row layernorm (D=1024) -> bf16 ----------------
__global__ void __launch_bounds__(256)
ln_rows_kernel(const float* __restrict__ x, const float* __restrict__ sc,
               const float* __restrict__ bi, bf16* __restrict__ out) {
    int row = blockIdx.x;
    const float* xr = x + (size_t)row * D_MODEL;
    int c = threadIdx.x * 4;
    float4 v = *reinterpret_cast<const float4*>(xr + c);
    float s = block_reduce_sum_256(v.x + v.y + v.z + v.w);
    float mu = s * (1.0f / D_MODEL);
    float dx = v.x - mu, dy = v.y - mu, dz = v.z - mu, dw = v.w - mu;
    float ss = block_reduce_sum_256(dx*dx + dy*dy + dz*dz + dw*dw);
    float inv = rsqrtf(ss * (1.0f / D_MODEL) + LN_EPS);
    float4 sv = *reinterpret_cast<const float4*>(sc + c);
    float4 bv = *reinterpret_cast<const float4*>(bi + c);
    __nv_bfloat162* o = reinterpret_cast<__nv_bfloat162*>(out + (size_t)row * D_MODEL + c);
    o[0] = __floats2bfloat162_rn(dx * inv * sv.x + bv.x, dy * inv * sv.y + bv.y);
    o[1] = __floats2bfloat162_rn(dz * inv * sv.z + bv.z, dw * inv * sv.w + bv.w);
}

// ---------------- final: LN(residual + gamma * att) -> fp32 ----------------
__global__ void __launch_bounds__(256)
final_ln_kernel(const float* __restrict__ resid, const float* __restrict__ att,
                const float* __restrict__ gamma, const float* __restrict__ sc,
                const float* __restrict__ bi, float* __restrict__ out) {
    int row = blockIdx.x;
    int c = threadIdx.x * 4;
    size_t off = (size_t)row * D_MODEL + c;
    float4 r = *reinterpret_cast<const float4*>(resid + off);
    float4 a = *reinterpret_cast<const float4*>(att + off);
    float4 g = *reinterpret_cast<const float4*>(gamma + c);
    float vx = r.x + g.x * a.x, vy = r.y + g.y * a.y;
    float vz = r.z + g.z * a.z, vw = r.w + g.w * a.w;
    float s = block_reduce_sum_256(vx + vy + vz + vw);
    float mu = s * (1.0f / D_MODEL);
    float dx = vx - mu, dy = vy - mu, dz = vz - mu, dw = vw - mu;
    float ss = block_reduce_sum_256(dx*dx + dy*dy + dz*dz + dw*dw);
    float inv = rsqrtf(ss * (1.0f / D_MODEL) + LN_EPS);
    float4 sv = *reinterpret_cast<const float4*>(sc + c);
    float4 bv = *reinterpret_cast<const float4*>(bi + c);
    float4 o;
    o.x = dx * inv * sv.x + bv.x;  o.y = dy * inv * sv.y + bv.y;
    o.z = dz * inv * sv.z + bv.z;  o.w = dw * inv * sv.w + bv.w;
    *reinterpret_cast<float4*>(out + off) = o;
}

// ---------------- per-head norm (Dh=64) + reshape to [B*H, N, 64] bf16 ---------
// mode 1: layernorm(qn/kn params) * SIG_SCALE ; mode 0: plain convert (V)
// proj row stride / column offset parametrized for the fused KV output.
__global__ void __launch_bounds__(256)
headnorm_kernel(const float* __restrict__ proj, int row_stride, int col_off,
                const float* __restrict__ sc, const float* __restrict__ bi,
                bf16* __restrict__ out, int mode) {
    int seg  = blockIdx.x * 8 + (threadIdx.x >> 5);   // one warp per (row, head)
    int lane = threadIdx.x & 31;
    int nrow = seg >> 4;            // / HEADS
    int h    = seg & 15;
    int b    = nrow >> 11;          // / N_SEQ
    int n    = nrow & (N_SEQ - 1);
    const float* p = proj + (size_t)nrow * row_stride + col_off + h * HEAD_DIM;
    float2 v = *reinterpret_cast<const float2*>(p + lane * 2);
    size_t oidx = ((size_t)(b * HEADS + h) * N_SEQ + n) * HEAD_DIM + lane * 2;
    if (mode == 0) {
        *reinterpret_cast<__nv_bfloat162*>(out + oidx) = __floats2bfloat162_rn(v.x, v.y);
        return;
    }
    float s = v.x + v.y;
#pragma unroll
    for (int o = 16; o > 0; o >>= 1) s += __shfl_xor_sync(0xffffffffu, s, o);
    float mu = s * (1.0f / HEAD_DIM);
    float dx = v.x - mu, dy = v.y - mu;
    float ss = dx * dx + dy * dy;
#pragma unroll
    for (int o = 16; o > 0; o >>= 1) ss += __shfl_xor_sync(0xffffffffu, ss, o);
    float inv = rsqrtf(ss * (1.0f / HEAD_DIM) + LN_EPS);
    float2 sv = *reinterpret_cast<const float2*>(sc + lane * 2);
    float2 bv = *reinterpret_cast<const float2*>(bi + lane * 2);
    float ox = (dx * inv * sv.x + bv.x) * SIG_SCALE;
    float oy = (dy * inv * sv.y + bv.y) * SIG_SCALE;
    *reinterpret_cast<__nv_bfloat162*>(out + oidx) = __floats2bfloat162_rn(ox, oy);
}

// ---------------- TN GEMM: C[M,N] = A[M,K] * B[N,K]^T  (bf16 in, fp32 out) -----
// 2-stage cp.async pipeline.
#define GBM 128
#define GBN 128
#define GBK 32
#define GPAD 40   // smem row pitch in bf16 elems (80B)

__global__ void __launch_bounds__(256)
gemm_tn_kernel(const bf16* __restrict__ A, const bf16* __restrict__ B,
               float* __restrict__ C, int M, int N, int K) {
    __shared__ __align__(128) bf16 As[2][GBM * GPAD];   // 2 x 10 KB
    __shared__ __align__(128) bf16 Bs[2][GBN * GPAD];   // 2 x 10 KB
    int bm = blockIdx.y * GBM, bn = blockIdx.x * GBN;
    int tid = threadIdx.x;
    int wid = tid >> 5;
    int wm = wid >> 1, wn = wid & 1;          // 4 x 2 warp grid -> 32 x 64 warp tile

    wmma::fragment<wmma::accumulator, 16, 16, 16, float> acc[2][4];
#pragma unroll
    for (int m = 0; m < 2; m++)
#pragma unroll
        for (int n = 0; n < 4; n++) wmma::fill_fragment(acc[m][n], 0.0f);

    const int r0 = tid >> 2, c0 = (tid & 3) * 8;   // 16B-chunk coords (row, col)

    // stage prefetch: 128 rows x 32 cols per operand = 512 chunks = 2/thread
    auto load_stage = [&](int k0, int buf) {
#pragma unroll
        for (int it = 0; it < 2; it++) {
            int r = r0 + it * 64;
            cp_async16(&As[buf][r * GPAD + c0], &A[(size_t)(bm + r) * K + k0 + c0]);
            cp_async16(&Bs[buf][r * GPAD + c0], &B[(size_t)(bn + r) * K + k0 + c0]);
        }
    };

    load_stage(0, 0);
    cp_commit();

    const int NT = K / GBK;
    int buf = 0;
    for (int t = 0; t < NT; t++) {
        if (t + 1 < NT) load_stage((t + 1) * GBK, buf ^ 1);
        cp_commit();
        cp_wait<1>();
        __syncthreads();
#pragma unroll
        for (int kk = 0; kk < GBK; kk += 16) {
            wmma::fragment<wmma::matrix_a, 16, 16, 16, bf16, wmma::row_major> af[2];
            wmma::fragment<wmma::matrix_b, 16, 16, 16, bf16, wmma::col_major> bfr[4];
#pragma unroll
            for (int m = 0; m < 2; m++)
                wmma::load_matrix_sync(af[m], &As[buf][(wm * 32 + m * 16) * GPAD + kk], GPAD);
#pragma unroll
            for (int n = 0; n < 4; n++)
                wmma::load_matrix_sync(bfr[n], &Bs[buf][(wn * 64 + n * 16) * GPAD + kk], GPAD);
#pragma unroll
            for (int m = 0; m < 2; m++)
#pragma unroll
                for (int n = 0; n < 4; n++)
                    wmma::mma_sync(acc[m][n], af[m], bfr[n], acc[m][n]);
        }
        __syncthreads();   // readers done before next prefetch overwrites this buf
        buf ^= 1;
    }
#pragma unroll
    for (int m = 0; m < 2; m++)
#pragma unroll
        for (int n = 0; n < 4; n++)
            wmma::store_matrix_sync(&C[(size_t)(bm + wm * 32 + m * 16) * N + bn + wn * 64 + n * 16],
                                    acc[m][n], N, wmma::mem_row_major);
}

// ---------------- fused sigmoid attention ----------------
// grid: (Nq/128, B*H), 256 threads (8 warps); each warp owns a 16-row Q strip.
// K/V tiles (64 rows) double-buffered with cp.async. Dynamic smem.
#define APADH 72   // bf16 pitch (144B)
#define APADF 68   // fp32 pitch (272B)
#define QTILE 128
#define KTILE 64

// smem layout offsets (bytes)
#define SA_Q   0
#define SA_K   (QTILE * APADH * 2)                         // 18432
#define SA_V   (SA_K + 2 * KTILE * APADH * 2)              // +18432
#define SA_SCR (SA_V + 2 * KTILE * APADH * 2)
#define SA_TOT (SA_SCR + 8 * 16 * APADF * 4)               // 90112 B

__global__ void __launch_bounds__(256)
attention_kernel(const bf16* __restrict__ qn, const bf16* __restrict__ kn,
                 const bf16* __restrict__ vt, bf16* __restrict__ ctx) {
    extern __shared__ __align__(128) char smem[];
    bf16*  Qs  = reinterpret_cast<bf16*>(smem + SA_Q);
    bf16*  Ks  = reinterpret_cast<bf16*>(smem + SA_K);     // 2 stages of KTILE*APADH
    bf16*  Vs  = reinterpret_cast<bf16*>(smem + SA_V);
    float* Scr = reinterpret_cast<float*>(smem + SA_SCR);

    int bh = blockIdx.y;
    int qb = blockIdx.x * QTILE;
    int b = bh >> 4, h = bh & 15;
    int tid = threadIdx.x, w = tid >> 5, lane = tid & 31;

    const bf16* qbase = qn + ((size_t)bh * N_SEQ + qb) * HEAD_DIM;
    const bf16* kbase = kn + (size_t)bh * N_SEQ * HEAD_DIM;
    const bf16* vbase = vt + (size_t)bh * N_SEQ * HEAD_DIM;

    const int r0 = tid >> 3, c0 = (tid & 7) * 8;   // 8 chunks per 64-elem row

    auto load_kv = [&](int kt, int buf) {
        bf16* kd = Ks + buf * KTILE * APADH;
        bf16* vd = Vs + buf * KTILE * APADH;
#pragma unroll
        for (int it = 0; it < 2; it++) {
            int r = r0 + it * 32;
            cp_async16(&kd[r * APADH + c0], &kbase[(size_t)(kt + r) * HEAD_DIM + c0]);
            cp_async16(&vd[r * APADH + c0], &vbase[(size_t)(kt + r) * HEAD_DIM + c0]);
        }
    };

    // prefetch K/V tile 0, then load Q synchronously (overlaps with async fill)
    load_kv(0, 0);
    cp_commit();
    for (int i = tid; i < QTILE * 8; i += 256) {     // 1024 chunks
        int r = i >> 3, c = (i & 7) * 8;
        *reinterpret_cast<uint4*>(&Qs[r * APADH + c]) =
            *reinterpret_cast<const uint4*>(&qbase[(size_t)r * HEAD_DIM + c]);
    }

    wmma::fragment<wmma::accumulator, 16, 16, 16, float> o_acc[4];
#pragma unroll
    for (int n = 0; n < 4; n++) wmma::fill_fragment(o_acc[n], 0.0f);

    float* myScr = Scr + w * 16 * APADF;
    bf16*  myP   = reinterpret_cast<bf16*>(myScr);          // 16 x APADH bf16 overlay

    const int NT = N_SEQ / KTILE;
    int buf = 0;
    for (int t = 0; t < NT; t++) {
        if (t + 1 < NT) load_kv((t + 1) * KTILE, buf ^ 1);
        cp_commit();
        cp_wait<1>();
        __syncthreads();
        const bf16* kS = Ks + buf * KTILE * APADH;
        const bf16* vS = Vs + buf * KTILE * APADH;

        // S = Q * K^T  (16 x 64 per warp)
        wmma::fragment<wmma::accumulator, 16, 16, 16, float> s_acc[4];
#pragma unroll
        for (int n = 0; n < 4; n++) wmma::fill_fragment(s_acc[n], 0.0f);
#pragma unroll
        for (int kk = 0; kk < 64; kk += 16) {
            wmma::fragment<wmma::matrix_a, 16, 16, 16, bf16, wmma::row_major> af;
            wmma::load_matrix_sync(af, &Qs[(w * 16) * APADH + kk], APADH);
#pragma unroll
            for (int n = 0; n < 4; n++) {
                wmma::fragment<wmma::matrix_b, 16, 16, 16, bf16, wmma::col_major> bfr;
                wmma::load_matrix_sync(bfr, &kS[(n * 16) * APADH + kk], APADH);
                wmma::mma_sync(s_acc[n], af, bfr, s_acc[n]);
            }
        }
        // sigmoid in registers (HW tanh.approx)
#pragma unroll
        for (int n = 0; n < 4; n++)
#pragma unroll
            for (int e = 0; e < s_acc[n].num_elements; e++)
                s_acc[n].x[e] = fast_sigmoid(s_acc[n].x[e] + ATT_BIAS);

        // re-fragment P: fp32 smem roundtrip -> bf16 matrix_a (per-warp private scratch)
#pragma unroll
        for (int n = 0; n < 4; n++)
            wmma::store_matrix_sync(myScr + n * 16, s_acc[n], APADF, wmma::mem_row_major);
        __syncwarp();
        float pv[32];
#pragma unroll
        for (int i = 0; i < 32; i++) {
            int idx = lane + i * 32;                       // 16 x 64 strip
            pv[i] = myScr[(idx >> 6) * APADF + (idx & 63)];
        }
        __syncwarp();
#pragma unroll
        for (int i = 0; i < 32; i++) {
            int idx = lane + i * 32;
            myP[(idx >> 6) * APADH + (idx & 63)] = __float2bfloat16(pv[i]);
        }
        __syncwarp();
        // O += P * V
#pragma unroll
        for (int kk = 0; kk < 64; kk += 16) {
            wmma::fragment<wmma::matrix_a, 16, 16, 16, bf16, wmma::row_major> pf;
            wmma::load_matrix_sync(pf, &myP[kk], APADH);
#pragma unroll
            for (int n = 0; n < 4; n++) {
                wmma::fragment<wmma::matrix_b, 16, 16, 16, bf16, wmma::row_major> vf;
                wmma::load_matrix_sync(vf, &vS[kk * APADH + n * 16], APADH);
                wmma::mma_sync(o_acc[n], pf, vf, o_acc[n]);
            }
        }
        __syncthreads();   // all reads of this buf done before next prefetch overwrites
        buf ^= 1;
    }

    // epilogue: O strip -> ctx bf16 in [B, Nq, H*64] layout
    __syncwarp();
#pragma unroll
    for (int n = 0; n < 4; n++)
        wmma::store_matrix_sync(myScr + n * 16, o_acc[n], APADF, wmma::mem_row_major);
    __syncwarp();
    bf16* cbase = ctx + ((size_t)(b * N_SEQ + qb + w * 16)) * D_MODEL + h * HEAD_DIM;
    for (int i = lane; i < 16 * 64; i += 32) {
        int r = i >> 6, c = i & 63;
        cbase[(size_t)r * D_MODEL + c] = __float2bfloat16(myScr[r * APADF + c]);
    }
}

// ---------------- host ----------------
static void* sym_addr(const void* sym) {
    void* p = nullptr;
    cudaGetSymbolAddress(&p, sym);
    return p;
}

extern "C" void kernel_launch(void* const* d_in, const int* in_sizes, int n_in,
                              void* d_out, int out_size) {
    const float* query_feats  = (const float*)d_in[0];
    const float* key_feats    = (const float*)d_in[1];
    const float* Wq           = (const float*)d_in[2];
    const float* Wk           = (const float*)d_in[3];
    const float* Wv           = (const float*)d_in[4];
    const float* Wo           = (const float*)d_in[5];
    const float* qn_scale     = (const float*)d_in[6];
    const float* qn_bias      = (const float*)d_in[7];
    const float* kn_scale     = (const float*)d_in[8];
    const float* kn_bias      = (const float*)d_in[9];
    const float* ln_q_scale   = (const float*)d_in[10];
    const float* ln_q_bias    = (const float*)d_in[11];
    const float* ln_out_scale = (const float*)d_in[12];
    const float* ln_out_bias  = (const float*)d_in[13];
    const float* gamma        = (const float*)d_in[14];
    float* out = (float*)d_out;

    bf16*  xq   = (bf16*) sym_addr(g_xq);
    bf16*  kf   = (bf16*) sym_addr(g_kf);
    bf16*  wq   = (bf16*) sym_addr(g_wq);
    bf16*  wkv  = (bf16*) sym_addr(g_wkv);
    bf16*  wo   = (bf16*) sym_addr(g_wo);
    float* proj = (float*)sym_addr(g_proj);
    bf16*  qn   = (bf16*) sym_addr(g_qn);
    bf16*  kn   = (bf16*) sym_addr(g_kn);
    bf16*  vt   = (bf16*) sym_addr(g_vt);
    bf16*  ctx  = (bf16*) sym_addr(g_ctx);

    const int featN4 = NROWS * D_MODEL / 4;      // 1,048,576 vec4
    const int wN4    = D_MODEL * D_MODEL / 4;    // 262,144 vec4

    // bf16 conversions (Wk|Wv stacked into one [2048,1024] matrix)
    convert_f2bf_kernel<<<featN4 / 256, 256>>>(key_feats, kf, featN4);
    convert_f2bf_kernel<<<wN4 / 256, 256>>>(Wq, wq, wN4);
    convert_f2bf_kernel<<<wN4 / 256, 256>>>(Wk, wkv, wN4);
    convert_f2bf_kernel<<<wN4 / 256, 256>>>(Wv, wkv + D_MODEL * D_MODEL, wN4);
    convert_f2bf_kernel<<<wN4 / 256, 256>>>(Wo, wo, wN4);

    // pre-LN of query
    ln_rows_kernel<<<NROWS, 256>>>(query_feats, ln_q_scale, ln_q_bias, xq);

    const int segBlocks = (NROWS * HEADS) / 8;   // 8192

    // Q projection + head-norm
    gemm_tn_kernel<<<dim3(D_MODEL / GBN, NROWS / GBM), 256>>>(xq, wq, proj, NROWS, D_MODEL, D_MODEL);
    headnorm_kernel<<<segBlocks, 256>>>(proj, D_MODEL, 0, qn_scale, qn_bias, qn, 1);

    // fused K|V projection (N=2048), then head-norm / reshape
    gemm_tn_kernel<<<dim3(2 * D_MODEL / GBN, NROWS / GBM), 256>>>(kf, wkv, proj, NROWS, 2 * D_MODEL, D_MODEL);
    headnorm_kernel<<<segBlocks, 256>>>(proj, 2 * D_MODEL, 0,       kn_scale, kn_bias, kn, 1);
    headnorm_kernel<<<segBlocks, 256>>>(proj, 2 * D_MODEL, D_MODEL, nullptr,  nullptr, vt, 0);

    // fused sigmoid attention (dynamic smem: 90112 B)
    cudaFuncSetAttribute(attention_kernel, cudaFuncAttributeMaxDynamicSharedMemorySize, SA_TOT);
    attention_kernel<<<dim3(N_SEQ / QTILE, BATCH * HEADS), 256, SA_TOT>>>(qn, kn, vt, ctx);

    // output projection
    gemm_tn_kernel<<<dim3(D_MODEL / GBN, NROWS / GBM), 256>>>(ctx, wo, proj, NROWS, D_MODEL, D_MODEL);

    // residual + gamma scale + post-LN
    final_ln_kernel<<<NROWS, 256>>>(query_feats, proj, gamma,
                                    ln_out_scale, ln_out_bias, out);
    (void)in_sizes; (void)n_in; (void)out_size;
}

// round 12
// speedup vs baseline: 1.0035x; 1.0006x over previous
#include <cuda_runtime.h>
#include <cuda_bf16.h>
#include <mma.h>
#include <math.h>
#include <cstdint>

using namespace nvcuda;
typedef __nv_bfloat16 bf16;

// ---------------- problem constants ----------------
#define D_MODEL 1024
#define N_SEQ   2048
#define BATCH   2
#define HEADS   16
#define HEAD_DIM 64
#define NROWS   (BATCH * N_SEQ)          // 4096
#define SIG_SCALE 0.35355339059327373f    // 64^-0.25
#define ATT_BIAS  (-3.0f)
#define LN_EPS    1e-5f

// ---------------- device scratch (static, alloc-guard-safe) ----------------
__device__ __align__(128) bf16  g_xq [NROWS * D_MODEL];             // LN(query) bf16
__device__ __align__(128) bf16  g_kf [NROWS * D_MODEL];             // key_feats bf16
__device__ __align__(128) bf16  g_wq [D_MODEL * D_MODEL];
__device__ __align__(128) bf16  g_wkv[2 * D_MODEL * D_MODEL];       // Wk rows 0..1023, Wv rows 1024..2047
__device__ __align__(128) bf16  g_wo [D_MODEL * D_MODEL];
__device__ __align__(128) float g_proj[NROWS * 2 * D_MODEL];        // fp32 GEMM out (fits N=2048)
__device__ __align__(128) bf16  g_qn [BATCH * HEADS * N_SEQ * HEAD_DIM];
__device__ __align__(128) bf16  g_kn [BATCH * HEADS * N_SEQ * HEAD_DIM];
__device__ __align__(128) bf16  g_vt [BATCH * HEADS * N_SEQ * HEAD_DIM];
__device__ __align__(128) bf16  g_ctx[NROWS * D_MODEL];

// ---------------- cp.async helpers ----------------
__device__ __forceinline__ void cp_async16(void* smem, const void* gmem) {
    unsigned int s = (unsigned int)__cvta_generic_to_shared(smem);
    asm volatile("cp.async.cg.shared.global [%0], [%1], 16;\n" :: "r"(s), "l"(gmem));
}
__device__ __forceinline__ void cp_commit() {
    asm volatile("cp.async.commit_group;\n" ::: "memory");
}
template<int N> __device__ __forceinline__ void cp_wait() {
    asm volatile("cp.async.wait_group %0;\n" :: "n"(N) : "memory");
}

__device__ __forceinline__ float fast_sigmoid(float x) {
    // sigmoid(x) = 0.5*(1+tanh(0.5x)) ; tanh.approx err ~2^-11, buried under gamma=1e-5
    float t;
    asm("tanh.approx.f32 %0, %1;" : "=f"(t) : "f"(x * 0.5f));
    return 0.5f * (1.0f + t);
}

// ---------------- helpers ----------------
__device__ __forceinline__ float block_reduce_sum_256(float v) {
    __shared__ float sh[8];
#pragma unroll
    for (int o = 16; o > 0; o >>= 1) v += __shfl_xor_sync(0xffffffffu, v, o);
    if ((threadIdx.x & 31) == 0) sh[threadIdx.x >> 5] = v;
    __syncthreads();
    float r = 0.f;
#pragma unroll
    for (int i = 0; i < 8; i++) r += sh[i];
    __syncthreads();
    return r;
}

// ---------------- elementwise convert fp32 -> bf16 ----------------
__global__ void convert_f2bf_kernel(const float* __restrict__ in,
                                    bf16* __restrict__ out, int n4) {
    int i = blockIdx.x * blockDim.x + threadIdx.x;
    if (i >= n4) return;
    float4 v = reinterpret_cast<const float4*>(in)[i];
    __nv_bfloat162* o = reinterpret_cast<__nv_bfloat162*>(out) + i * 2;
    o[0] = __floats2bfloat162_rn(v.x, v.y);
    o[1] = __floats2bfloat162_rn(v.z, v.w);
}

// ---------------- row layernorm (D=1024) -> bf16 ----------------
__global__ void __launch_bounds__(256)
ln_rows_kernel(const float* __restrict__ x, const float* __restrict__ sc,
               const float* __restrict__ bi, bf16* __restrict__ out) {
    int row = blockIdx.x;
    const float* xr = x + (size_t)row * D_MODEL;
    int c = threadIdx.x * 4;
    float4 v = *reinterpret_cast<const float4*>(xr + c);
    float s = block_reduce_sum_256(v.x + v.y + v.z + v.w);
    float mu = s * (1.0f / D_MODEL);
    float dx = v.x - mu, dy = v.y - mu, dz = v.z - mu, dw = v.w - mu;
    float ss = block_reduce_sum_256(dx*dx + dy*dy + dz*dz + dw*dw);
    float inv = rsqrtf(ss * (1.0f / D_MODEL) + LN_EPS);
    float4 sv = *reinterpret_cast<const float4*>(sc + c);
    float4 bv = *reinterpret_cast<const float4*>(bi + c);
    __nv_bfloat162* o = reinterpret_cast<__nv_bfloat162*>(out + (size_t)row * D_MODEL + c);
    o[0] = __floats2bfloat162_rn(dx * inv * sv.x + bv.x, dy * inv * sv.y + bv.y);
    o[1] = __floats2bfloat162_rn(dz * inv * sv.z + bv.z, dw * inv * sv.w + bv.w);
}

// ---------------- final: LN(residual + gamma * att) -> fp32 ----------------
__global__ void __launch_bounds__(256)
final_ln_kernel(const float* __restrict__ resid, const float* __restrict__ att,
                const float* __restrict__ gamma, const float* __restrict__ sc,
                const float* __restrict__ bi, float* __restrict__ out) {
    int row = blockIdx.x;
    int c = threadIdx.x * 4;
    size_t off = (size_t)row * D_MODEL + c;
    float4 r = *reinterpret_cast<const float4*>(resid + off);
    float4 a = *reinterpret_cast<const float4*>(att + off);
    float4 g = *reinterpret_cast<const float4*>(gamma + c);
    float vx = r.x + g.x * a.x, vy = r.y + g.y * a.y;
    float vz = r.z + g.z * a.z, vw = r.w + g.w * a.w;
    float s = block_reduce_sum_256(vx + vy + vz + vw);
    float mu = s * (1.0f / D_MODEL);
    float dx = vx - mu, dy = vy - mu, dz = vz - mu, dw = vw - mu;
    float ss = block_reduce_sum_256(dx*dx + dy*dy + dz*dz + dw*dw);
    float inv = rsqrtf(ss * (1.0f / D_MODEL) + LN_EPS);
    float4 sv = *reinterpret_cast<const float4*>(sc + c);
    float4 bv = *reinterpret_cast<const float4*>(bi + c);
    float4 o;
    o.x = dx * inv * sv.x + bv.x;  o.y = dy * inv * sv.y + bv.y;
    o.z = dz * inv * sv.z + bv.z;  o.w = dw * inv * sv.w + bv.w;
    *reinterpret_cast<float4*>(out + off) = o;
}

// ---------------- per-head norm (Dh=64) + reshape to [B*H, N, 64] bf16 ---------
// mode 1: layernorm(qn/kn params) * SIG_SCALE ; mode 0: plain convert (V)
// proj row stride / column offset parametrized for the fused KV output.
__global__ void __launch_bounds__(256)
headnorm_kernel(const float* __restrict__ proj, int row_stride, int col_off,
                const float* __restrict__ sc, const float* __restrict__ bi,
                bf16* __restrict__ out, int mode) {
    int seg  = blockIdx.x * 8 + (threadIdx.x >> 5);   // one warp per (row, head)
    int lane = threadIdx.x & 31;
    int nrow = seg >> 4;            // / HEADS
    int h    = seg & 15;
    int b    = nrow >> 11;          // / N_SEQ
    int n    = nrow & (N_SEQ - 1);
    const float* p = proj + (size_t)nrow * row_stride + col_off + h * HEAD_DIM;
    float2 v = *reinterpret_cast<const float2*>(p + lane * 2);
    size_t oidx = ((size_t)(b * HEADS + h) * N_SEQ + n) * HEAD_DIM + lane * 2;
    if (mode == 0) {
        *reinterpret_cast<__nv_bfloat162*>(out + oidx) = __floats2bfloat162_rn(v.x, v.y);
        return;
    }
    float s = v.x + v.y;
#pragma unroll
    for (int o = 16; o > 0; o >>= 1) s += __shfl_xor_sync(0xffffffffu, s, o);
    float mu = s * (1.0f / HEAD_DIM);
    float dx = v.x - mu, dy = v.y - mu;
    float ss = dx * dx + dy * dy;
#pragma unroll
    for (int o = 16; o > 0; o >>= 1) ss += __shfl_xor_sync(0xffffffffu, ss, o);
    float inv = rsqrtf(ss * (1.0f / HEAD_DIM) + LN_EPS);
    float2 sv = *reinterpret_cast<const float2*>(sc + lane * 2);
    float2 bv = *reinterpret_cast<const float2*>(bi + lane * 2);
    float ox = (dx * inv * sv.x + bv.x) * SIG_SCALE;
    float oy = (dy * inv * sv.y + bv.y) * SIG_SCALE;
    *reinterpret_cast<__nv_bfloat162*>(out + oidx) = __floats2bfloat162_rn(ox, oy);
}

// ---------------- TN GEMM: C[M,N] = A[M,K] * B[N,K]^T  (bf16 in, fp32 out) -----
// 2-stage cp.async pipeline.
#define GBM 128
#define GBN 128
#define GBK 32
#define GPAD 40   // smem row pitch in bf16 elems (80B)

__global__ void __launch_bounds__(256)
gemm_tn_kernel(const bf16* __restrict__ A, const bf16* __restrict__ B,
               float* __restrict__ C, int M, int N, int K) {
    __shared__ __align__(128) bf16 As[2][GBM * GPAD];   // 2 x 10 KB
    __shared__ __align__(128) bf16 Bs[2][GBN * GPAD];   // 2 x 10 KB
    int bm = blockIdx.y * GBM, bn = blockIdx.x * GBN;
    int tid = threadIdx.x;
    int wid = tid >> 5;
    int wm = wid >> 1, wn = wid & 1;          // 4 x 2 warp grid -> 32 x 64 warp tile

    wmma::fragment<wmma::accumulator, 16, 16, 16, float> acc[2][4];
#pragma unroll
    for (int m = 0; m < 2; m++)
#pragma unroll
        for (int n = 0; n < 4; n++) wmma::fill_fragment(acc[m][n], 0.0f);

    const int r0 = tid >> 2, c0 = (tid & 3) * 8;   // 16B-chunk coords (row, col)

    // stage prefetch: 128 rows x 32 cols per operand = 512 chunks = 2/thread
    auto load_stage = [&](int k0, int buf) {
#pragma unroll
        for (int it = 0; it < 2; it++) {
            int r = r0 + it * 64;
            cp_async16(&As[buf][r * GPAD + c0], &A[(size_t)(bm + r) * K + k0 + c0]);
            cp_async16(&Bs[buf][r * GPAD + c0], &B[(size_t)(bn + r) * K + k0 + c0]);
        }
    };

    load_stage(0, 0);
    cp_commit();

    const int NT = K / GBK;
    int buf = 0;
    for (int t = 0; t < NT; t++) {
        if (t + 1 < NT) load_stage((t + 1) * GBK, buf ^ 1);
        cp_commit();
        cp_wait<1>();
        __syncthreads();
#pragma unroll
        for (int kk = 0; kk < GBK; kk += 16) {
            wmma::fragment<wmma::matrix_a, 16, 16, 16, bf16, wmma::row_major> af[2];
            wmma::fragment<wmma::matrix_b, 16, 16, 16, bf16, wmma::col_major> bfr[4];
#pragma unroll
            for (int m = 0; m < 2; m++)
                wmma::load_matrix_sync(af[m], &As[buf][(wm * 32 + m * 16) * GPAD + kk], GPAD);
#pragma unroll
            for (int n = 0; n < 4; n++)
                wmma::load_matrix_sync(bfr[n], &Bs[buf][(wn * 64 + n * 16) * GPAD + kk], GPAD);
#pragma unroll
            for (int m = 0; m < 2; m++)
#pragma unroll
                for (int n = 0; n < 4; n++)
                    wmma::mma_sync(acc[m][n], af[m], bfr[n], acc[m][n]);
        }
        __syncthreads();   // readers done before next prefetch overwrites this buf
        buf ^= 1;
    }
#pragma unroll
    for (int m = 0; m < 2; m++)
#pragma unroll
        for (int n = 0; n < 4; n++)
            wmma::store_matrix_sync(&C[(size_t)(bm + wm * 32 + m * 16) * N + bn + wn * 64 + n * 16],
                                    acc[m][n], N, wmma::mem_row_major);
}

// ---------------- fused sigmoid attention ----------------
// grid: (Nq/128, B*H), 256 threads (8 warps); each warp owns a 16-row Q strip.
// K/V tiles (64 rows) double-buffered with cp.async. Dynamic smem.
#define APADH 72   // bf16 pitch (144B)
#define APADF 68   // fp32 pitch (272B)
#define QTILE 128
#define KTILE 64

// smem layout offsets (bytes)
#define SA_Q   0
#define SA_K   (QTILE * APADH * 2)                         // 18432
#define SA_V   (SA_K + 2 * KTILE * APADH * 2)              // +18432
#define SA_SCR (SA_V + 2 * KTILE * APADH * 2)
#define SA_TOT (SA_SCR + 8 * 16 * APADF * 4)               // 90112 B

__global__ void __launch_bounds__(256)
attention_kernel(const bf16* __restrict__ qn, const bf16* __restrict__ kn,
                 const bf16* __restrict__ vt, bf16* __restrict__ ctx) {
    extern __shared__ __align__(128) char smem[];
    bf16*  Qs  = reinterpret_cast<bf16*>(smem + SA_Q);
    bf16*  Ks  = reinterpret_cast<bf16*>(smem + SA_K);     // 2 stages of KTILE*APADH
    bf16*  Vs  = reinterpret_cast<bf16*>(smem + SA_V);
    float* Scr = reinterpret_cast<float*>(smem + SA_SCR);

    int bh = blockIdx.y;
    int qb = blockIdx.x * QTILE;
    int b = bh >> 4, h = bh & 15;
    int tid = threadIdx.x, w = tid >> 5, lane = tid & 31;

    const bf16* qbase = qn + ((size_t)bh * N_SEQ + qb) * HEAD_DIM;
    const bf16* kbase = kn + (size_t)bh * N_SEQ * HEAD_DIM;
    const bf16* vbase = vt + (size_t)bh * N_SEQ * HEAD_DIM;

    const int r0 = tid >> 3, c0 = (tid & 7) * 8;   // 8 chunks per 64-elem row

    auto load_kv = [&](int kt, int buf) {
        bf16* kd = Ks + buf * KTILE * APADH;
        bf16* vd = Vs + buf * KTILE * APADH;
#pragma unroll
        for (int it = 0; it < 2; it++) {
            int r = r0 + it * 32;
            cp_async16(&kd[r * APADH + c0], &kbase[(size_t)(kt + r) * HEAD_DIM + c0]);
            cp_async16(&vd[r * APADH + c0], &vbase[(size_t)(kt + r) * HEAD_DIM + c0]);
        }
    };

    // prefetch K/V tile 0, then load Q synchronously (overlaps with async fill)
    load_kv(0, 0);
    cp_commit();
    for (int i = tid; i < QTILE * 8; i += 256) {     // 1024 chunks
        int r = i >> 3, c = (i & 7) * 8;
        *reinterpret_cast<uint4*>(&Qs[r * APADH + c]) =
            *reinterpret_cast<const uint4*>(&qbase[(size_t)r * HEAD_DIM + c]);
    }

    wmma::fragment<wmma::accumulator, 16, 16, 16, float> o_acc[4];
#pragma unroll
    for (int n = 0; n < 4; n++) wmma::fill_fragment(o_acc[n], 0.0f);

    float* myScr = Scr + w * 16 * APADF;
    bf16*  myP   = reinterpret_cast<bf16*>(myScr);          // 16 x APADH bf16 overlay

    const int NT = N_SEQ / KTILE;
    int buf = 0;
    for (int t = 0; t < NT; t++) {
        if (t + 1 < NT) load_kv((t + 1) * KTILE, buf ^ 1);
        cp_commit();
        cp_wait<1>();
        __syncthreads();
        const bf16* kS = Ks + buf * KTILE * APADH;
        const bf16* vS = Vs + buf * KTILE * APADH;

        // S = Q * K^T  (16 x 64 per warp)
        wmma::fragment<wmma::accumulator, 16, 16, 16, float> s_acc[4];
#pragma unroll
        for (int n = 0; n < 4; n++) wmma::fill_fragment(s_acc[n], 0.0f);
#pragma unroll
        for (int kk = 0; kk < 64; kk += 16) {
            wmma::fragment<wmma::matrix_a, 16, 16, 16, bf16, wmma::row_major> af;
            wmma::load_matrix_sync(af, &Qs[(w * 16) * APADH + kk], APADH);
#pragma unroll
            for (int n = 0; n < 4; n++) {
                wmma::fragment<wmma::matrix_b, 16, 16, 16, bf16, wmma::col_major> bfr;
                wmma::load_matrix_sync(bfr, &kS[(n * 16) * APADH + kk], APADH);
                wmma::mma_sync(s_acc[n], af, bfr, s_acc[n]);
            }
        }
        // sigmoid in registers (HW tanh.approx)
#pragma unroll
        for (int n = 0; n < 4; n++)
#pragma unroll
            for (int e = 0; e < s_acc[n].num_elements; e++)
                s_acc[n].x[e] = fast_sigmoid(s_acc[n].x[e] + ATT_BIAS);

        // re-fragment P: fp32 smem roundtrip -> bf16 matrix_a (per-warp private scratch)
#pragma unroll
        for (int n = 0; n < 4; n++)
            wmma::store_matrix_sync(myScr + n * 16, s_acc[n], APADF, wmma::mem_row_major);
        __syncwarp();
        float pv[32];
#pragma unroll
        for (int i = 0; i < 32; i++) {
            int idx = lane + i * 32;                       // 16 x 64 strip
            pv[i] = myScr[(idx >> 6) * APADF + (idx & 63)];
        }
        __syncwarp();
#pragma unroll
        for (int i = 0; i < 32; i++) {
            int idx = lane + i * 32;
            myP[(idx >> 6) * APADH + (idx & 63)] = __float2bfloat16(pv[i]);
        }
        __syncwarp();
        // O += P * V
#pragma unroll
        for (int kk = 0; kk < 64; kk += 16) {
            wmma::fragment<wmma::matrix_a, 16, 16, 16, bf16, wmma::row_major> pf;
            wmma::load_matrix_sync(pf, &myP[kk], APADH);
#pragma unroll
            for (int n = 0; n < 4; n++) {
                wmma::fragment<wmma::matrix_b, 16, 16, 16, bf16, wmma::row_major> vf;
                wmma::load_matrix_sync(vf, &vS[kk * APADH + n * 16], APADH);
                wmma::mma_sync(o_acc[n], pf, vf, o_acc[n]);
            }
        }
        __syncthreads();   // all reads of this buf done before next prefetch overwrites
        buf ^= 1;
    }

    // epilogue: O strip -> ctx bf16 in [B, Nq, H*64] layout
    __syncwarp();
#pragma unroll
    for (int n = 0; n < 4; n++)
        wmma::store_matrix_sync(myScr + n * 16, o_acc[n], APADF, wmma::mem_row_major);
    __syncwarp();
    bf16* cbase = ctx + ((size_t)(b * N_SEQ + qb + w * 16)) * D_MODEL + h * HEAD_DIM;
    for (int i = lane; i < 16 * 64; i += 32) {
        int r = i >> 6, c = i & 63;
        cbase[(size_t)r * D_MODEL + c] = __float2bfloat16(myScr[r * APADF + c]);
    }
}

// ---------------- host ----------------
static void* sym_addr(const void* sym) {
    void* p = nullptr;
    cudaGetSymbolAddress(&p, sym);
    return p;
}

extern "C" void kernel_launch(void* const* d_in, const int* in_sizes, int n_in,
                              void* d_out, int out_size) {
    const float* query_feats  = (const float*)d_in[0];
    const float* key_feats    = (const float*)d_in[1];
    const float* Wq           = (const float*)d_in[2];
    const float* Wk           = (const float*)d_in[3];
    const float* Wv           = (const float*)d_in[4];
    const float* Wo           = (const float*)d_in[5];
    const float* qn_scale     = (const float*)d_in[6];
    const float* qn_bias      = (const float*)d_in[7];
    const float* kn_scale     = (const float*)d_in[8];
    const float* kn_bias      = (const float*)d_in[9];
    const float* ln_q_scale   = (const float*)d_in[10];
    const float* ln_q_bias    = (const float*)d_in[11];
    const float* ln_out_scale = (const float*)d_in[12];
    const float* ln_out_bias  = (const float*)d_in[13];
    const float* gamma        = (const float*)d_in[14];
    float* out = (float*)d_out;

    bf16*  xq   = (bf16*) sym_addr(g_xq);
    bf16*  kf   = (bf16*) sym_addr(g_kf);
    bf16*  wq   = (bf16*) sym_addr(g_wq);
    bf16*  wkv  = (bf16*) sym_addr(g_wkv);
    bf16*  wo   = (bf16*) sym_addr(g_wo);
    float* proj = (float*)sym_addr(g_proj);
    bf16*  qn   = (bf16*) sym_addr(g_qn);
    bf16*  kn   = (bf16*) sym_addr(g_kn);
    bf16*  vt   = (bf16*) sym_addr(g_vt);
    bf16*  ctx  = (bf16*) sym_addr(g_ctx);

    const int featN4 = NROWS * D_MODEL / 4;      // 1,048,576 vec4
    const int wN4    = D_MODEL * D_MODEL / 4;    // 262,144 vec4

    // bf16 conversions (Wk|Wv stacked into one [2048,1024] matrix)
    convert_f2bf_kernel<<<featN4 / 256, 256>>>(key_feats, kf, featN4);
    convert_f2bf_kernel<<<wN4 / 256, 256>>>(Wq, wq, wN4);
    convert_f2bf_kernel<<<wN4 / 256, 256>>>(Wk, wkv, wN4);
    convert_f2bf_kernel<<<wN4 / 256, 256>>>(Wv, wkv + D_MODEL * D_MODEL, wN4);
    convert_f2bf_kernel<<<wN4 / 256, 256>>>(Wo, wo, wN4);

    // pre-LN of query
    ln_rows_kernel<<<NROWS, 256>>>(query_feats, ln_q_scale, ln_q_bias, xq);

    const int segBlocks = (NROWS * HEADS) / 8;   // 8192

    // Q projection + head-norm
    gemm_tn_kernel<<<dim3(D_MODEL / GBN, NROWS / GBM), 256>>>(xq, wq, proj, NROWS, D_MODEL, D_MODEL);
    headnorm_kernel<<<segBlocks, 256>>>(proj, D_MODEL, 0, qn_scale, qn_bias, qn, 1);

    // fused K|V projection (N=2048), then head-norm / reshape
    gemm_tn_kernel<<<dim3(2 * D_MODEL / GBN, NROWS / GBM), 256>>>(kf, wkv, proj, NROWS, 2 * D_MODEL, D_MODEL);
    headnorm_kernel<<<segBlocks, 256>>>(proj, 2 * D_MODEL, 0,       kn_scale, kn_bias, kn, 1);
    headnorm_kernel<<<segBlocks, 256>>>(proj, 2 * D_MODEL, D_MODEL, nullptr,  nullptr, vt, 0);

    // fused sigmoid attention (dynamic smem: 90112 B)
    cudaFuncSetAttribute(attention_kernel, cudaFuncAttributeMaxDynamicSharedMemorySize, SA_TOT);
    attention_kernel<<<dim3(N_SEQ / QTILE, BATCH * HEADS), 256, SA_TOT>>>(qn, kn, vt, ctx);

    // output projection
    gemm_tn_kernel<<<dim3(D_MODEL / GBN, NROWS / GBM), 256>>>(ctx, wo, proj, NROWS, D_MODEL, D_MODEL);

    // residual + gamma scale + post-LN
    final_ln_kernel<<<NROWS, 256>>>(query_feats, proj, gamma,
                                    ln_out_scale, ln_out_bias, out);
    (void)in_sizes; (void)n_in; (void)out_size;
}

// round 14
// speedup vs baseline: 1.0041x; 1.0006x over previous
#include <cuda_runtime.h>
#include <cuda_bf16.h>
#include <mma.h>
#include <math.h>
#include <cstdint>

using namespace nvcuda;
typedef __nv_bfloat16 bf16;

// ---------------- problem constants ----------------
#define D_MODEL 1024
#define N_SEQ   2048
#define BATCH   2
#define HEADS   16
#define HEAD_DIM 64
#define NROWS   (BATCH * N_SEQ)          // 4096
#define SIG_SCALE 0.35355339059327373f    // 64^-0.25
#define ATT_BIAS  (-3.0f)
#define LN_EPS    1e-5f

// ---------------- device scratch (static, alloc-guard-safe) ----------------
__device__ __align__(128) bf16  g_xq [NROWS * D_MODEL];             // LN(query) bf16
__device__ __align__(128) bf16  g_kf [NROWS * D_MODEL];             // key_feats bf16
__device__ __align__(128) bf16  g_wq [D_MODEL * D_MODEL];
__device__ __align__(128) bf16  g_wkv[2 * D_MODEL * D_MODEL];       // Wk rows 0..1023, Wv rows 1024..2047
__device__ __align__(128) bf16  g_wo [D_MODEL * D_MODEL];
__device__ __align__(128) float g_proj[NROWS * 2 * D_MODEL];        // fp32 GEMM out (fits N=2048)
__device__ __align__(128) bf16  g_qn [BATCH * HEADS * N_SEQ * HEAD_DIM];
__device__ __align__(128) bf16  g_kn [BATCH * HEADS * N_SEQ * HEAD_DIM];
__device__ __align__(128) bf16  g_vt [BATCH * HEADS * N_SEQ * HEAD_DIM];
__device__ __align__(128) bf16  g_ctx[NROWS * D_MODEL];

// ---------------- cp.async helpers ----------------
__device__ __forceinline__ void cp_async16(void* smem, const void* gmem) {
    unsigned int s = (unsigned int)__cvta_generic_to_shared(smem);
    asm volatile("cp.async.cg.shared.global [%0], [%1], 16;\n" :: "r"(s), "l"(gmem));
}
__device__ __forceinline__ void cp_commit() {
    asm volatile("cp.async.commit_group;\n" ::: "memory");
}
template<int N> __device__ __forceinline__ void cp_wait() {
    asm volatile("cp.async.wait_group %0;\n" :: "n"(N) : "memory");
}

__device__ __forceinline__ float fast_sigmoid(float x) {
    // sigmoid(x) = 0.5*(1+tanh(0.5x)) ; tanh.approx err ~2^-11, buried under gamma=1e-5
    float t;
    asm("tanh.approx.f32 %0, %1;" : "=f"(t) : "f"(x * 0.5f));
    return 0.5f * (1.0f + t);
}

// ---------------- helpers ----------------
__device__ __forceinline__ float block_reduce_sum_256(float v) {
    __shared__ float sh[8];
#pragma unroll
    for (int o = 16; o > 0; o >>= 1) v += __shfl_xor_sync(0xffffffffu, v, o);
    if ((threadIdx.x & 31) == 0) sh[threadIdx.x >> 5] = v;
    __syncthreads();
    float r = 0.f;
#pragma unroll
    for (int i = 0; i < 8; i++) r += sh[i];
    __syncthreads();
    return r;
}

// ---------------- elementwise convert fp32 -> bf16 ----------------
__global__ void convert_f2bf_kernel(const float* __restrict__ in,
                                    bf16* __restrict__ out, int n4) {
    int i = blockIdx.x * blockDim.x + threadIdx.x;
    if (i >= n4) return;
    float4 v = reinterpret_cast<const float4*>(in)[i];
    __nv_bfloat162* o = reinterpret_cast<__nv_bfloat162*>(out) + i * 2;
    o[0] = __floats2bfloat162_rn(v.x, v.y);
    o[1] = __floats2bfloat162_rn(v.z, v.w);
}

// ---------------- row layernorm (D=1024) -> bf16 ----------------
__global__ void __launch_bounds__(256)
ln_rows_kernel(const float* __restrict__ x, const float* __restrict__ sc,
               const float* __restrict__ bi, bf16* __restrict__ out) {
    int row = blockIdx.x;
    const float* xr = x + (size_t)row * D_MODEL;
    int c = threadIdx.x * 4;
    float4 v = *reinterpret_cast<const float4*>(xr + c);
    float s = block_reduce_sum_256(v.x + v.y + v.z + v.w);
    float mu = s * (1.0f / D_MODEL);
    float dx = v.x - mu, dy = v.y - mu, dz = v.z - mu, dw = v.w - mu;
    float ss = block_reduce_sum_256(dx*dx + dy*dy + dz*dz + dw*dw);
    float inv = rsqrtf(ss * (1.0f / D_MODEL) + LN_EPS);
    float4 sv = *reinterpret_cast<const float4*>(sc + c);
    float4 bv = *reinterpret_cast<const float4*>(bi + c);
    __nv_bfloat162* o = reinterpret_cast<__nv_bfloat162*>(out + (size_t)row * D_MODEL + c);
    o[0] = __floats2bfloat162_rn(dx * inv * sv.x + bv.x, dy * inv * sv.y + bv.y);
    o[1] = __floats2bfloat162_rn(dz * inv * sv.z + bv.z, dw * inv * sv.w + bv.w);
}

// ---------------- final: LN(residual + gamma * att) -> fp32 ----------------
__global__ void __launch_bounds__(256)
final_ln_kernel(const float* __restrict__ resid, const float* __restrict__ att,
                const float* __restrict__ gamma, const float* __restrict__ sc,
                const float* __restrict__ bi, float* __restrict__ out) {
    int row = blockIdx.x;
    int c = threadIdx.x * 4;
    size_t off = (size_t)row * D_MODEL + c;
    float4 r = *reinterpret_cast<const float4*>(resid + off);
    float4 a = *reinterpret_cast<const float4*>(att + off);
    float4 g = *reinterpret_cast<const float4*>(gamma + c);
    float vx = r.x + g.x * a.x, vy = r.y + g.y * a.y;
    float vz = r.z + g.z * a.z, vw = r.w + g.w * a.w;
    float s = block_reduce_sum_256(vx + vy + vz + vw);
    float mu = s * (1.0f / D_MODEL);
    float dx = vx - mu, dy = vy - mu, dz = vz - mu, dw = vw - mu;
    float ss = block_reduce_sum_256(dx*dx + dy*dy + dz*dz + dw*dw);
    float inv = rsqrtf(ss * (1.0f / D_MODEL) + LN_EPS);
    float4 sv = *reinterpret_cast<const float4*>(sc + c);
    float4 bv = *reinterpret_cast<const float4*>(bi + c);
    float4 o;
    o.x = dx * inv * sv.x + bv.x;  o.y = dy * inv * sv.y + bv.y;
    o.z = dz * inv * sv.z + bv.z;  o.w = dw * inv * sv.w + bv.w;
    *reinterpret_cast<float4*>(out + off) = o;
}

// ---------------- per-head norm (Dh=64) + reshape to [B*H, N, 64] bf16 ---------
// mode 1: layernorm(qn/kn params) * SIG_SCALE ; mode 0: plain convert (V)
// proj row stride / column offset parametrized for the fused KV output.
__global__ void __launch_bounds__(256)
headnorm_kernel(const float* __restrict__ proj, int row_stride, int col_off,
                const float* __restrict__ sc, const float* __restrict__ bi,
                bf16* __restrict__ out, int mode) {
    int seg  = blockIdx.x * 8 + (threadIdx.x >> 5);   // one warp per (row, head)
    int lane = threadIdx.x & 31;
    int nrow = seg >> 4;            // / HEADS
    int h    = seg & 15;
    int b    = nrow >> 11;          // / N_SEQ
    int n    = nrow & (N_SEQ - 1);
    const float* p = proj + (size_t)nrow * row_stride + col_off + h * HEAD_DIM;
    float2 v = *reinterpret_cast<const float2*>(p + lane * 2);
    size_t oidx = ((size_t)(b * HEADS + h) * N_SEQ + n) * HEAD_DIM + lane * 2;
    if (mode == 0) {
        *reinterpret_cast<__nv_bfloat162*>(out + oidx) = __floats2bfloat162_rn(v.x, v.y);
        return;
    }
    float s = v.x + v.y;
#pragma unroll
    for (int o = 16; o > 0; o >>= 1) s += __shfl_xor_sync(0xffffffffu, s, o);
    float mu = s * (1.0f / HEAD_DIM);
    float dx = v.x - mu, dy = v.y - mu;
    float ss = dx * dx + dy * dy;
#pragma unroll
    for (int o = 16; o > 0; o >>= 1) ss += __shfl_xor_sync(0xffffffffu, ss, o);
    float inv = rsqrtf(ss * (1.0f / HEAD_DIM) + LN_EPS);
    float2 sv = *reinterpret_cast<const float2*>(sc + lane * 2);
    float2 bv = *reinterpret_cast<const float2*>(bi + lane * 2);
    float ox = (dx * inv * sv.x + bv.x) * SIG_SCALE;
    float oy = (dy * inv * sv.y + bv.y) * SIG_SCALE;
    *reinterpret_cast<__nv_bfloat162*>(out + oidx) = __floats2bfloat162_rn(ox, oy);
}

// ---------------- TN GEMM: C[M,N] = A[M,K] * B[N,K]^T  (bf16 in, fp32 out) -----
// 2-stage cp.async pipeline.
#define GBM 128
#define GBN 128
#define GBK 32
#define GPAD 40   // smem row pitch in bf16 elems (80B)

__global__ void __launch_bounds__(256)
gemm_tn_kernel(const bf16* __restrict__ A, const bf16* __restrict__ B,
               float* __restrict__ C, int M, int N, int K) {
    __shared__ __align__(128) bf16 As[2][GBM * GPAD];   // 2 x 10 KB
    __shared__ __align__(128) bf16 Bs[2][GBN * GPAD];   // 2 x 10 KB
    int bm = blockIdx.y * GBM, bn = blockIdx.x * GBN;
    int tid = threadIdx.x;
    int wid = tid >> 5;
    int wm = wid >> 1, wn = wid & 1;          // 4 x 2 warp grid -> 32 x 64 warp tile

    wmma::fragment<wmma::accumulator, 16, 16, 16, float> acc[2][4];
#pragma unroll
    for (int m = 0; m < 2; m++)
#pragma unroll
        for (int n = 0; n < 4; n++) wmma::fill_fragment(acc[m][n], 0.0f);

    const int r0 = tid >> 2, c0 = (tid & 3) * 8;   // 16B-chunk coords (row, col)

    // stage prefetch: 128 rows x 32 cols per operand = 512 chunks = 2/thread
    auto load_stage = [&](int k0, int buf) {
#pragma unroll
        for (int it = 0; it < 2; it++) {
            int r = r0 + it * 64;
            cp_async16(&As[buf][r * GPAD + c0], &A[(size_t)(bm + r) * K + k0 + c0]);
            cp_async16(&Bs[buf][r * GPAD + c0], &B[(size_t)(bn + r) * K + k0 + c0]);
        }
    };

    load_stage(0, 0);
    cp_commit();

    const int NT = K / GBK;
    int buf = 0;
    for (int t = 0; t < NT; t++) {
        if (t + 1 < NT) load_stage((t + 1) * GBK, buf ^ 1);
        cp_commit();
        cp_wait<1>();
        __syncthreads();
#pragma unroll
        for (int kk = 0; kk < GBK; kk += 16) {
            wmma::fragment<wmma::matrix_a, 16, 16, 16, bf16, wmma::row_major> af[2];
            wmma::fragment<wmma::matrix_b, 16, 16, 16, bf16, wmma::col_major> bfr[4];
#pragma unroll
            for (int m = 0; m < 2; m++)
                wmma::load_matrix_sync(af[m], &As[buf][(wm * 32 + m * 16) * GPAD + kk], GPAD);
#pragma unroll
            for (int n = 0; n < 4; n++)
                wmma::load_matrix_sync(bfr[n], &Bs[buf][(wn * 64 + n * 16) * GPAD + kk], GPAD);
#pragma unroll
            for (int m = 0; m < 2; m++)
#pragma unroll
                for (int n = 0; n < 4; n++)
                    wmma::mma_sync(acc[m][n], af[m], bfr[n], acc[m][n]);
        }
        __syncthreads();   // readers done before next prefetch overwrites this buf
        buf ^= 1;
    }
#pragma unroll
    for (int m = 0; m < 2; m++)
#pragma unroll
        for (int n = 0; n < 4; n++)
            wmma::store_matrix_sync(&C[(size_t)(bm + wm * 32 + m * 16) * N + bn + wn * 64 + n * 16],
                                    acc[m][n], N, wmma::mem_row_major);
}

// ---------------- fused sigmoid attention ----------------
// grid: (Nq/128, B*H), 256 threads (8 warps); each warp owns a 16-row Q strip.
// K/V tiles (64 rows) double-buffered with cp.async. Dynamic smem.
#define APADH 72   // bf16 pitch (144B)
#define APADF 68   // fp32 pitch (272B)
#define QTILE 128
#define KTILE 64

// smem layout offsets (bytes)
#define SA_Q   0
#define SA_K   (QTILE * APADH * 2)                         // 18432
#define SA_V   (SA_K + 2 * KTILE * APADH * 2)              // +18432
#define SA_SCR (SA_V + 2 * KTILE * APADH * 2)
#define SA_TOT (SA_SCR + 8 * 16 * APADF * 4)               // 90112 B

__global__ void __launch_bounds__(256)
attention_kernel(const bf16* __restrict__ qn, const bf16* __restrict__ kn,
                 const bf16* __restrict__ vt, bf16* __restrict__ ctx) {
    extern __shared__ __align__(128) char smem[];
    bf16*  Qs  = reinterpret_cast<bf16*>(smem + SA_Q);
    bf16*  Ks  = reinterpret_cast<bf16*>(smem + SA_K);     // 2 stages of KTILE*APADH
    bf16*  Vs  = reinterpret_cast<bf16*>(smem + SA_V);
    float* Scr = reinterpret_cast<float*>(smem + SA_SCR);

    int bh = blockIdx.y;
    int qb = blockIdx.x * QTILE;
    int b = bh >> 4, h = bh & 15;
    int tid = threadIdx.x, w = tid >> 5, lane = tid & 31;

    const bf16* qbase = qn + ((size_t)bh * N_SEQ + qb) * HEAD_DIM;
    const bf16* kbase = kn + (size_t)bh * N_SEQ * HEAD_DIM;
    const bf16* vbase = vt + (size_t)bh * N_SEQ * HEAD_DIM;

    const int r0 = tid >> 3, c0 = (tid & 7) * 8;   // 8 chunks per 64-elem row

    auto load_kv = [&](int kt, int buf) {
        bf16* kd = Ks + buf * KTILE * APADH;
        bf16* vd = Vs + buf * KTILE * APADH;
#pragma unroll
        for (int it = 0; it < 2; it++) {
            int r = r0 + it * 32;
            cp_async16(&kd[r * APADH + c0], &kbase[(size_t)(kt + r) * HEAD_DIM + c0]);
            cp_async16(&vd[r * APADH + c0], &vbase[(size_t)(kt + r) * HEAD_DIM + c0]);
        }
    };

    // prefetch K/V tile 0, then load Q synchronously (overlaps with async fill)
    load_kv(0, 0);
    cp_commit();
    for (int i = tid; i < QTILE * 8; i += 256) {     // 1024 chunks
        int r = i >> 3, c = (i & 7) * 8;
        *reinterpret_cast<uint4*>(&Qs[r * APADH + c]) =
            *reinterpret_cast<const uint4*>(&qbase[(size_t)r * HEAD_DIM + c]);
    }

    wmma::fragment<wmma::accumulator, 16, 16, 16, float> o_acc[4];
#pragma unroll
    for (int n = 0; n < 4; n++) wmma::fill_fragment(o_acc[n], 0.0f);

    float* myScr = Scr + w * 16 * APADF;
    bf16*  myP   = reinterpret_cast<bf16*>(myScr);          // 16 x APADH bf16 overlay

    const int NT = N_SEQ / KTILE;
    int buf = 0;
    for (int t = 0; t < NT; t++) {
        if (t + 1 < NT) load_kv((t + 1) * KTILE, buf ^ 1);
        cp_commit();
        cp_wait<1>();
        __syncthreads();
        const bf16* kS = Ks + buf * KTILE * APADH;
        const bf16* vS = Vs + buf * KTILE * APADH;

        // S = Q * K^T  (16 x 64 per warp)
        wmma::fragment<wmma::accumulator, 16, 16, 16, float> s_acc[4];
#pragma unroll
        for (int n = 0; n < 4; n++) wmma::fill_fragment(s_acc[n], 0.0f);
#pragma unroll
        for (int kk = 0; kk < 64; kk += 16) {
            wmma::fragment<wmma::matrix_a, 16, 16, 16, bf16, wmma::row_major> af;
            wmma::load_matrix_sync(af, &Qs[(w * 16) * APADH + kk], APADH);
#pragma unroll
            for (int n = 0; n < 4; n++) {
                wmma::fragment<wmma::matrix_b, 16, 16, 16, bf16, wmma::col_major> bfr;
                wmma::load_matrix_sync(bfr, &kS[(n * 16) * APADH + kk], APADH);
                wmma::mma_sync(s_acc[n], af, bfr, s_acc[n]);
            }
        }
        // sigmoid in registers (HW tanh.approx)
#pragma unroll
        for (int n = 0; n < 4; n++)
#pragma unroll
            for (int e = 0; e < s_acc[n].num_elements; e++)
                s_acc[n].x[e] = fast_sigmoid(s_acc[n].x[e] + ATT_BIAS);

        // re-fragment P: fp32 smem roundtrip -> bf16 matrix_a (per-warp private scratch)
#pragma unroll
        for (int n = 0; n < 4; n++)
            wmma::store_matrix_sync(myScr + n * 16, s_acc[n], APADF, wmma::mem_row_major);
        __syncwarp();
        float pv[32];
#pragma unroll
        for (int i = 0; i < 32; i++) {
            int idx = lane + i * 32;                       // 16 x 64 strip
            pv[i] = myScr[(idx >> 6) * APADF + (idx & 63)];
        }
        __syncwarp();
#pragma unroll
        for (int i = 0; i < 32; i++) {
            int idx = lane + i * 32;
            myP[(idx >> 6) * APADH + (idx & 63)] = __float2bfloat16(pv[i]);
        }
        __syncwarp();
        // O += P * V
#pragma unroll
        for (int kk = 0; kk < 64; kk += 16) {
            wmma::fragment<wmma::matrix_a, 16, 16, 16, bf16, wmma::row_major> pf;
            wmma::load_matrix_sync(pf, &myP[kk], APADH);
#pragma unroll
            for (int n = 0; n < 4; n++) {
                wmma::fragment<wmma::matrix_b, 16, 16, 16, bf16, wmma::row_major> vf;
                wmma::load_matrix_sync(vf, &vS[kk * APADH + n * 16], APADH);
                wmma::mma_sync(o_acc[n], pf, vf, o_acc[n]);
            }
        }
        __syncthreads();   // all reads of this buf done before next prefetch overwrites
        buf ^= 1;
    }

    // epilogue: O strip -> ctx bf16 in [B, Nq, H*64] layout
    __syncwarp();
#pragma unroll
    for (int n = 0; n < 4; n++)
        wmma::store_matrix_sync(myScr + n * 16, o_acc[n], APADF, wmma::mem_row_major);
    __syncwarp();
    bf16* cbase = ctx + ((size_t)(b * N_SEQ + qb + w * 16)) * D_MODEL + h * HEAD_DIM;
    for (int i = lane; i < 16 * 64; i += 32) {
        int r = i >> 6, c = i & 63;
        cbase[(size_t)r * D_MODEL + c] = __float2bfloat16(myScr[r * APADF + c]);
    }
}

// ---------------- host ----------------
static void* sym_addr(const void* sym) {
    void* p = nullptr;
    cudaGetSymbolAddress(&p, sym);
    return p;
}

extern "C" void kernel_launch(void* const* d_in, const int* in_sizes, int n_in,
                              void* d_out, int out_size) {
    const float* query_feats  = (const float*)d_in[0];
    const float* key_feats    = (const float*)d_in[1];
    const float* Wq           = (const float*)d_in[2];
    const float* Wk           = (const float*)d_in[3];
    const float* Wv           = (const float*)d_in[4];
    const float* Wo           = (const float*)d_in[5];
    const float* qn_scale     = (const float*)d_in[6];
    const float* qn_bias      = (const float*)d_in[7];
    const float* kn_scale     = (const float*)d_in[8];
    const float* kn_bias      = (const float*)d_in[9];
    const float* ln_q_scale   = (const float*)d_in[10];
    const float* ln_q_bias    = (const float*)d_in[11];
    const float* ln_out_scale = (const float*)d_in[12];
    const float* ln_out_bias  = (const float*)d_in[13];
    const float* gamma        = (const float*)d_in[14];
    float* out = (float*)d_out;

    bf16*  xq   = (bf16*) sym_addr(g_xq);
    bf16*  kf   = (bf16*) sym_addr(g_kf);
    bf16*  wq   = (bf16*) sym_addr(g_wq);
    bf16*  wkv  = (bf16*) sym_addr(g_wkv);
    bf16*  wo   = (bf16*) sym_addr(g_wo);
    float* proj = (float*)sym_addr(g_proj);
    bf16*  qn   = (bf16*) sym_addr(g_qn);
    bf16*  kn   = (bf16*) sym_addr(g_kn);
    bf16*  vt   = (bf16*) sym_addr(g_vt);
    bf16*  ctx  = (bf16*) sym_addr(g_ctx);

    const int featN4 = NROWS * D_MODEL / 4;      // 1,048,576 vec4
    const int wN4    = D_MODEL * D_MODEL / 4;    // 262,144 vec4

    // bf16 conversions (Wk|Wv stacked into one [2048,1024] matrix)
    convert_f2bf_kernel<<<featN4 / 256, 256>>>(key_feats, kf, featN4);
    convert_f2bf_kernel<<<wN4 / 256, 256>>>(Wq, wq, wN4);
    convert_f2bf_kernel<<<wN4 / 256, 256>>>(Wk, wkv, wN4);
    convert_f2bf_kernel<<<wN4 / 256, 256>>>(Wv, wkv + D_MODEL * D_MODEL, wN4);
    convert_f2bf_kernel<<<wN4 / 256, 256>>>(Wo, wo, wN4);

    // pre-LN of query
    ln_rows_kernel<<<NROWS, 256>>>(query_feats, ln_q_scale, ln_q_bias, xq);

    const int segBlocks = (NROWS * HEADS) / 8;   // 8192

    // Q projection + head-norm
    gemm_tn_kernel<<<dim3(D_MODEL / GBN, NROWS / GBM), 256>>>(xq, wq, proj, NROWS, D_MODEL, D_MODEL);
    headnorm_kernel<<<segBlocks, 256>>>(proj, D_MODEL, 0, qn_scale, qn_bias, qn, 1);

    // fused K|V projection (N=2048), then head-norm / reshape
    gemm_tn_kernel<<<dim3(2 * D_MODEL / GBN, NROWS / GBM), 256>>>(kf, wkv, proj, NROWS, 2 * D_MODEL, D_MODEL);
    headnorm_kernel<<<segBlocks, 256>>>(proj, 2 * D_MODEL, 0,       kn_scale, kn_bias, kn, 1);
    headnorm_kernel<<<segBlocks, 256>>>(proj, 2 * D_MODEL, D_MODEL, nullptr,  nullptr, vt, 0);

    // fused sigmoid attention (dynamic smem: 90112 B)
    cudaFuncSetAttribute(attention_kernel, cudaFuncAttributeMaxDynamicSharedMemorySize, SA_TOT);
    attention_kernel<<<dim3(N_SEQ / QTILE, BATCH * HEADS), 256, SA_TOT>>>(qn, kn, vt, ctx);

    // output projection
    gemm_tn_kernel<<<dim3(D_MODEL / GBN, NROWS / GBM), 256>>>(ctx, wo, proj, NROWS, D_MODEL, D_MODEL);

    // residual + gamma scale + post-LN
    final_ln_kernel<<<NROWS, 256>>>(query_feats, proj, gamma,
                                    ln_out_scale, ln_out_bias, out);
    (void)in_sizes; (void)n_in; (void)out_size;
}